// round 12
// baseline (speedup 1.0000x reference)
#include <cuda_runtime.h>
#include <cuda_fp16.h>
#include <math.h>
#include <stdint.h>

#define D_MODEL 1024
#define N_HEADS 16
#define D_HEAD  64
#define D_MLP   4096
#define BATCH   2
#define SEQ     2048
#define NTOK    (BATCH*SEQ)   // 4096
#define LN_EPS  1e-5f

// ---------------------------------------------------------------------------
// scratch (static device globals; no allocation)
// ---------------------------------------------------------------------------
__device__ __half g_ln1[NTOK*D_MODEL];
__device__ __half g_q  [NTOK*D_MODEL];
__device__ __half g_k  [NTOK*D_MODEL];
__device__ __half g_v  [NTOK*D_MODEL];
__device__ __half g_z  [NTOK*D_MODEL];
__device__ float  g_rmid[NTOK*D_MODEL];
__device__ __half g_ln2[NTOK*D_MODEL];
__device__ __half g_mlp[(size_t)NTOK*D_MLP];
// transposed fp16 weights ([N,K] row-major, k-contiguous)
__device__ __half g_wqkv[3*D_MODEL*D_MODEL];     // rows 0..1023 Q, 1024..2047 K, 2048..3071 V
__device__ __half g_wo  [D_MODEL*D_MODEL];
__device__ __half g_win [(size_t)D_MLP*D_MODEL];
__device__ __half g_wout[(size_t)D_MODEL*D_MLP];

// ---------------------------------------------------------------------------
// helpers
// ---------------------------------------------------------------------------
__device__ __forceinline__ uint32_t smem_to_u32(const void* p) {
    uint32_t a;
    asm("{ .reg .u64 t; cvta.to.shared.u64 t, %1; cvt.u32.u64 %0, t; }" : "=r"(a) : "l"(p));
    return a;
}
__device__ __forceinline__ void cp16(uint32_t s, const void* g) {
    asm volatile("cp.async.cg.shared.global [%0], [%1], 16;" :: "r"(s), "l"(g));
}
__device__ __forceinline__ void ldmx4(uint32_t* r, uint32_t addr) {
    asm volatile("ldmatrix.sync.aligned.m8n8.x4.shared.b16 {%0,%1,%2,%3}, [%4];"
        : "=r"(r[0]), "=r"(r[1]), "=r"(r[2]), "=r"(r[3]) : "r"(addr));
}
__device__ __forceinline__ void ldmx4t(uint32_t* r, uint32_t addr) {
    asm volatile("ldmatrix.sync.aligned.m8n8.x4.trans.shared.b16 {%0,%1,%2,%3}, [%4];"
        : "=r"(r[0]), "=r"(r[1]), "=r"(r[2]), "=r"(r[3]) : "r"(addr));
}
__device__ __forceinline__ void mma16816(float* d, const uint32_t* a, uint32_t b0, uint32_t b1) {
    asm volatile("mma.sync.aligned.m16n8k16.row.col.f32.f16.f16.f32 "
        "{%0,%1,%2,%3}, {%4,%5,%6,%7}, {%8,%9}, {%0,%1,%2,%3};"
        : "+f"(d[0]), "+f"(d[1]), "+f"(d[2]), "+f"(d[3])
        : "r"(a[0]), "r"(a[1]), "r"(a[2]), "r"(a[3]), "r"(b0), "r"(b1));
}
__device__ __forceinline__ uint32_t packh2(float x, float y) {
    __half2 h = __floats2half2_rn(x, y);
    return *(uint32_t*)&h;
}

// ---------------------------------------------------------------------------
// merged weight transpose: ALL weights in one launch (3072 blocks).
// src [K,N] fp32 row-major -> dst [N,K] fp16 (k-contiguous), 64x64 tiles.
//   blocks [0,768):    QKV  (48 head-segs x 16 k-tiles)
//   blocks [768,1024): W_O  (16 n x 16 k)
//   blocks [1024,2048):W_in (64 n x 16 k)
//   blocks [2048,3072):W_out(16 n x 64 k)
// ---------------------------------------------------------------------------
__global__ void transpose_all(const float* __restrict__ WQ, const float* __restrict__ WK,
                              const float* __restrict__ WV, const float* __restrict__ WO,
                              const float* __restrict__ Win, const float* __restrict__ Wout,
                              __half* __restrict__ wqkv, __half* __restrict__ wo,
                              __half* __restrict__ win, __half* __restrict__ wout) {
    __shared__ float t[64][65];
    const int bid = blockIdx.x;
    const float* src; __half* dst;
    int K, N, n0, k0;
    if (bid < 768) {
        int z = bid >> 4, kt = bid & 15;
        int seg = z >> 4, head = z & 15;
        src = (seg == 0 ? WQ : seg == 1 ? WK : WV) + (size_t)head * 1024 * 64;
        dst = wqkv + (size_t)seg * 1024 * 1024 + (size_t)head * 64 * 1024;
        K = 1024; N = 64; n0 = 0; k0 = kt * 64;
    } else if (bid < 1024) {
        int tt = bid - 768; n0 = (tt & 15) * 64; k0 = (tt >> 4) * 64;
        src = WO; dst = wo; K = 1024; N = 1024;
    } else if (bid < 2048) {
        int tt = bid - 1024; n0 = (tt & 63) * 64; k0 = (tt >> 6) * 64;
        src = Win; dst = win; K = 1024; N = 4096;
    } else {
        int tt = bid - 2048; n0 = (tt & 15) * 64; k0 = (tt >> 4) * 64;
        src = Wout; dst = wout; K = 4096; N = 1024;
    }
    const int tid = threadIdx.x;
    {
        int c4 = tid & 15, r = tid >> 4;
#pragma unroll
        for (int i = 0; i < 4; i++) {
            float4 v = *(const float4*)(src + (size_t)(k0 + r + i*16) * N + n0 + c4*4);
            t[r + i*16][c4*4+0] = v.x;
            t[r + i*16][c4*4+1] = v.y;
            t[r + i*16][c4*4+2] = v.z;
            t[r + i*16][c4*4+3] = v.w;
        }
    }
    __syncthreads();
    {
        int kg = (tid & 7) * 8;
#pragma unroll
        for (int p = 0; p < 2; p++) {
            int n = (tid >> 3) + p*32;
            __half h[8];
#pragma unroll
            for (int q = 0; q < 8; q++) h[q] = __float2half_rn(t[kg + q][n]);
            *(uint4*)(dst + (size_t)(n0 + n) * K + k0 + kg) = *(uint4*)h;
        }
    }
}

// ---------------------------------------------------------------------------
// LayerNorm -> fp16
// ---------------------------------------------------------------------------
__global__ void ln_h_kernel(const float* __restrict__ x, const float* __restrict__ w,
                            const float* __restrict__ b, __half* __restrict__ o) {
    int row = blockIdx.x;
    const float* xr = x + (size_t)row * D_MODEL;
    float vals[4];
    float s = 0.f, s2 = 0.f;
#pragma unroll
    for (int i = 0; i < 4; i++) {
        float v = xr[threadIdx.x + i*256];
        vals[i] = v; s += v; s2 += v*v;
    }
#pragma unroll
    for (int off = 16; off > 0; off >>= 1) {
        s  += __shfl_xor_sync(0xFFFFFFFFu, s,  off);
        s2 += __shfl_xor_sync(0xFFFFFFFFu, s2, off);
    }
    __shared__ float sh[2][8];
    int wid = threadIdx.x >> 5, lid = threadIdx.x & 31;
    if (lid == 0) { sh[0][wid] = s; sh[1][wid] = s2; }
    __syncthreads();
    s = 0.f; s2 = 0.f;
#pragma unroll
    for (int i = 0; i < 8; i++) { s += sh[0][i]; s2 += sh[1][i]; }
    float mean = s * (1.f/(float)D_MODEL);
    float var  = s2 * (1.f/(float)D_MODEL) - mean*mean;
    float rstd = rsqrtf(var + LN_EPS);
#pragma unroll
    for (int i = 0; i < 4; i++) {
        int c = threadIdx.x + i*256;
        float v = (vals[i] - mean) * rstd * w[c] + b[c];
        o[(size_t)row * D_MODEL + c] = __float2half_rn(v);
    }
}

// ---------------------------------------------------------------------------
// fp16 HMMA GEMM: C[M,N] = A[M,K] @ B^T  (B stored [N,K] fp16)
// CTA tile 128x128, BK=32, 256 threads (8 warps 2x4, 64x32/warp),
// 4-stage cp.async pipeline (uniform commit, wait_group 2),
// ONE __syncthreads per k-iteration, 2 CTAs/SM.
// MODE 1: fp32 C0 = acc + bias + res
// MODE 2: fp16 Ch0 = relu(acc + bias)
// MODE 3: fp16 Ch{0,1,2} = acc + bias   (SEG: segment-select by bn>>10, ldc=1024)
// ---------------------------------------------------------------------------
#define TILE_B    10240              // 128 rows * 80 bytes
#define STAGE_B   (2*TILE_B)         // A + B tiles
#define NSTAGE    4
#define GEMM_SMEM (NSTAGE*STAGE_B)   // 81920

template<int MODE, bool SEG>
__global__ void __launch_bounds__(256, 2) gemm_h(
    const __half* __restrict__ A, const __half* __restrict__ B,
    const float* __restrict__ b0, const float* __restrict__ b1, const float* __restrict__ b2,
    const float* __restrict__ res,
    float* __restrict__ C0,
    __half* __restrict__ Ch0, __half* __restrict__ Ch1, __half* __restrict__ Ch2,
    int M, int N, int K)
{
    extern __shared__ __align__(128) char smem[];
    const uint32_t sbase = smem_to_u32(smem);
    const int tid  = threadIdx.x;
    const int lane = tid & 31;
    const int wid  = tid >> 5;
    const int wm   = wid >> 2;           // 0..1 -> m offset 64*wm
    const int wn   = wid & 3;            // 0..3 -> n offset 32*wn
    const int bm   = blockIdx.y * 128;
    const int bn   = blockIdx.x * 128;

    const float* bias = b0;
    __half* Chx = Ch0;
    int bnl = bn, ldc = N;
    if (SEG) {
        int sg = bn >> 10;
        bias = (sg == 0) ? b0 : (sg == 1) ? b1 : b2;
        Chx  = (sg == 0) ? Ch0 : (sg == 1) ? Ch1 : Ch2;
        bnl  = bn & 1023;
        ldc  = 1024;
    }

    float acc[4][4][4];
#pragma unroll
    for (int i = 0; i < 4; i++)
#pragma unroll
        for (int j = 0; j < 4; j++)
#pragma unroll
            for (int q = 0; q < 4; q++) acc[i][j][q] = 0.f;

    const int nk = K >> 5;

    auto load_stage = [&](int kt, int buf) {
        const int k0 = kt << 5;
        const uint32_t sb0 = sbase + buf * STAGE_B;
#pragma unroll
        for (int u = 0; u < 2; u++) {
            int f   = tid + u * 256;
            int row = f >> 2, c = f & 3;
            uint32_t soff = (uint32_t)(row * 80 + c * 16);
            cp16(sb0 + 0*TILE_B + soff, A + (size_t)(bm + row) * K + k0 + c * 8);
            cp16(sb0 + 1*TILE_B + soff, B + (size_t)(bn + row) * K + k0 + c * 8);
        }
    };

    const uint32_t aRowOff = (uint32_t)((wm*64 + (lane & 15)) * 80 + (lane >> 4) * 16);
    const uint32_t bRowOff = (uint32_t)((wn*32 + (lane & 15)) * 80 + (lane >> 4) * 16);

    // prologue: stages 0,1,2 (K >= 1024 so nk >= 32 > 3)
    load_stage(0, 0);
    asm volatile("cp.async.commit_group;");
    load_stage(1, 1);
    asm volatile("cp.async.commit_group;");
    load_stage(2, 2);
    asm volatile("cp.async.commit_group;");

    for (int kt = 0; kt < nk; kt++) {
        // uniform pipeline: one commit/iter => stage kt resident after wait_group 2
        asm volatile("cp.async.wait_group 2;" ::: "memory");
        __syncthreads();   // also proves all warps done compute(kt-1)

        const uint32_t sb0 = sbase + (uint32_t)(kt % NSTAGE) * STAGE_B;
#pragma unroll
        for (int ks = 0; ks < 2; ks++) {
            const uint32_t koff = ks * 32;
            uint32_t a[4][4], bb[2][4];
#pragma unroll
            for (int i = 0; i < 4; i++)
                ldmx4(a[i], sb0 + 0*TILE_B + aRowOff + (uint32_t)(i*16*80) + koff);
#pragma unroll
            for (int j = 0; j < 2; j++)
                ldmx4(bb[j], sb0 + 1*TILE_B + bRowOff + (uint32_t)(j*16*80) + koff);
#pragma unroll
            for (int i = 0; i < 4; i++)
#pragma unroll
                for (int nb = 0; nb < 4; nb++) {
                    int j = nb >> 1, sel = nb & 1;
                    mma16816(acc[i][nb], a[i], bb[j][sel], bb[j][sel + 2]);
                }
        }

        if (kt + 3 < nk) load_stage(kt + 3, (kt + 3) % NSTAGE);
        asm volatile("cp.async.commit_group;");   // empty group at tail keeps count uniform
    }

    // --- epilogue ---
    const int mrow = bm + wm*64 + (lane >> 2);
    const int ncol = bnl + wn*32 + (lane & 3) * 2;
#pragma unroll
    for (int i = 0; i < 4; i++) {
#pragma unroll
        for (int jj = 0; jj < 4; jj++) {
            int r0 = mrow + i*16;
            int c  = ncol + jj*8;
            float2 bv = *(const float2*)(bias + c);
            float x0 = acc[i][jj][0] + bv.x;
            float x1 = acc[i][jj][1] + bv.y;
            float x2 = acc[i][jj][2] + bv.x;
            float x3 = acc[i][jj][3] + bv.y;
            if (MODE == 2) {
                x0 = fmaxf(x0, 0.f); x1 = fmaxf(x1, 0.f);
                x2 = fmaxf(x2, 0.f); x3 = fmaxf(x3, 0.f);
                *(__half2*)(Chx + (size_t)r0 * ldc + c)     = __floats2half2_rn(x0, x1);
                *(__half2*)(Chx + (size_t)(r0+8) * ldc + c) = __floats2half2_rn(x2, x3);
            } else if (MODE == 3) {
                *(__half2*)(Chx + (size_t)r0 * ldc + c)     = __floats2half2_rn(x0, x1);
                *(__half2*)(Chx + (size_t)(r0+8) * ldc + c) = __floats2half2_rn(x2, x3);
            } else {
                float2 rv0 = *(const float2*)(res + (size_t)r0 * ldc + c);
                float2 rv1 = *(const float2*)(res + (size_t)(r0+8) * ldc + c);
                x0 += rv0.x; x1 += rv0.y; x2 += rv1.x; x3 += rv1.y;
                *(float2*)(C0 + (size_t)r0 * ldc + c)     = make_float2(x0, x1);
                *(float2*)(C0 + (size_t)(r0+8) * ldc + c) = make_float2(x2, x3);
            }
        }
    }
}

// ---------------------------------------------------------------------------
// HMMA flash attention (fp16 in, fp32 accum, causal) -> fp16 z
// ---------------------------------------------------------------------------
__global__ void __launch_bounds__(128) attn_hmma(
    const __half* __restrict__ Q, const __half* __restrict__ K,
    const __half* __restrict__ V, __half* __restrict__ Z)
{
    __shared__ __align__(16) __half sQ[64*72];
    __shared__ __align__(16) __half sK[2][64*72];
    __shared__ __align__(16) __half sV[2][64*72];
    const int tid = threadIdx.x, lane = tid & 31, wid = tid >> 5;
    const int qblk = (SEQ/64 - 1) - blockIdx.x;     // heavy blocks first
    const int bh = blockIdx.y, b = bh >> 4, h = bh & 15;
    const uint32_t uQ = smem_to_u32(sQ);
    const uint32_t uK = smem_to_u32(sK);
    const uint32_t uV = smem_to_u32(sV);
    const size_t qbase = ((size_t)(b*SEQ + qblk*64)) * D_MODEL + h * D_HEAD;

    for (int f = tid; f < 512; f += 128) {
        int row = f >> 3, c = f & 7;
        cp16(uQ + row*144 + c*16, Q + qbase + (size_t)row * D_MODEL + c*8);
    }
    auto load_kv = [&](int kt, int buf) {
        size_t base = ((size_t)(b*SEQ + kt*64)) * D_MODEL + h * D_HEAD;
        for (int f = tid; f < 512; f += 128) {
            int row = f >> 3, c = f & 7;
            cp16(uK + buf*(64*144) + row*144 + c*16, K + base + (size_t)row * D_MODEL + c*8);
            cp16(uV + buf*(64*144) + row*144 + c*16, V + base + (size_t)row * D_MODEL + c*8);
        }
    };
    load_kv(0, 0);
    asm volatile("cp.async.commit_group;");

    float oacc[8][4];
#pragma unroll
    for (int i = 0; i < 8; i++)
#pragma unroll
        for (int c = 0; c < 4; c++) oacc[i][c] = 0.f;
    float m0 = -INFINITY, m1 = -INFINITY, l0 = 0.f, l1 = 0.f;
    uint32_t a[4][4];

    const int ntiles = qblk + 1;
    for (int kt = 0; kt < ntiles; kt++) {
        if (kt + 1 < ntiles) {
            load_kv(kt + 1, (kt + 1) & 1);
            asm volatile("cp.async.commit_group;");
            asm volatile("cp.async.wait_group 1;");
        } else {
            asm volatile("cp.async.wait_group 0;");
        }
        __syncthreads();

        if (kt == 0) {
#pragma unroll
            for (int kk = 0; kk < 4; kk++)
                ldmx4(a[kk], uQ + (uint32_t)((wid*16 + (lane & 15))*144 + kk*32 + (lane >> 4)*16));
        }

        // S = Q K^T
        const uint32_t kb0 = uK + (uint32_t)((kt & 1) * (64*144));
        float sc[8][4];
#pragma unroll
        for (int i = 0; i < 8; i++)
#pragma unroll
            for (int c = 0; c < 4; c++) sc[i][c] = 0.f;
#pragma unroll
        for (int kk = 0; kk < 4; kk++) {
            uint32_t kb[4][4];
#pragma unroll
            for (int j = 0; j < 4; j++)
                ldmx4(kb[j], kb0 + (uint32_t)((j*16 + (lane & 15))*144 + kk*32 + (lane >> 4)*16));
#pragma unroll
            for (int j = 0; j < 4; j++) {
                mma16816(sc[2*j],   a[kk], kb[j][0], kb[j][2]);
                mma16816(sc[2*j+1], a[kk], kb[j][1], kb[j][3]);
            }
        }

        // softmax (online)
        const float scale = 0.125f;   // 1/sqrt(64)
        const bool diag = (kt == qblk);
        const int q0 = wid*16 + (lane >> 2);
        float mx0 = m0, mx1 = m1;
#pragma unroll
        for (int nb = 0; nb < 8; nb++) {
#pragma unroll
            for (int c = 0; c < 4; c++) {
                float s = sc[nb][c] * scale;
                if (diag) {
                    int jg = nb*8 + (lane & 3)*2 + (c & 1);
                    int qg = q0 + ((c >> 1) << 3);
                    if (jg > qg) s = -INFINITY;
                }
                sc[nb][c] = s;
            }
            mx0 = fmaxf(mx0, fmaxf(sc[nb][0], sc[nb][1]));
            mx1 = fmaxf(mx1, fmaxf(sc[nb][2], sc[nb][3]));
        }
        mx0 = fmaxf(mx0, __shfl_xor_sync(0xFFFFFFFFu, mx0, 1));
        mx0 = fmaxf(mx0, __shfl_xor_sync(0xFFFFFFFFu, mx0, 2));
        mx1 = fmaxf(mx1, __shfl_xor_sync(0xFFFFFFFFu, mx1, 1));
        mx1 = fmaxf(mx1, __shfl_xor_sync(0xFFFFFFFFu, mx1, 2));
        float fac0 = __expf(m0 - mx0), fac1 = __expf(m1 - mx1);
        m0 = mx0; m1 = mx1;
        float ls0 = 0.f, ls1 = 0.f;
#pragma unroll
        for (int nb = 0; nb < 8; nb++) {
            sc[nb][0] = __expf(sc[nb][0] - mx0);
            sc[nb][1] = __expf(sc[nb][1] - mx0);
            sc[nb][2] = __expf(sc[nb][2] - mx1);
            sc[nb][3] = __expf(sc[nb][3] - mx1);
            ls0 += sc[nb][0] + sc[nb][1];
            ls1 += sc[nb][2] + sc[nb][3];
        }
        l0 = l0 * fac0 + ls0;
        l1 = l1 * fac1 + ls1;
#pragma unroll
        for (int nb = 0; nb < 8; nb++) {
            oacc[nb][0] *= fac0; oacc[nb][1] *= fac0;
            oacc[nb][2] *= fac1; oacc[nb][3] *= fac1;
        }

        // O += P V
        const uint32_t vb0 = uV + (uint32_t)((kt & 1) * (64*144));
#pragma unroll
        for (int kk = 0; kk < 4; kk++) {
            uint32_t pa[4];
            pa[0] = packh2(sc[2*kk][0],   sc[2*kk][1]);
            pa[1] = packh2(sc[2*kk][2],   sc[2*kk][3]);
            pa[2] = packh2(sc[2*kk+1][0], sc[2*kk+1][1]);
            pa[3] = packh2(sc[2*kk+1][2], sc[2*kk+1][3]);
#pragma unroll
            for (int j = 0; j < 4; j++) {
                uint32_t vb[4];
                ldmx4t(vb, vb0 + (uint32_t)((kk*16 + (lane & 15))*144 + j*32 + (lane >> 4)*16));
                mma16816(oacc[2*j],   pa, vb[0], vb[1]);
                mma16816(oacc[2*j+1], pa, vb[2], vb[3]);
            }
        }
        __syncthreads();
    }

    // normalize + store
    l0 += __shfl_xor_sync(0xFFFFFFFFu, l0, 1);
    l0 += __shfl_xor_sync(0xFFFFFFFFu, l0, 2);
    l1 += __shfl_xor_sync(0xFFFFFFFFu, l1, 1);
    l1 += __shfl_xor_sync(0xFFFFFFFFu, l1, 2);
    float i0 = 1.f / l0, i1 = 1.f / l1;
    size_t tok0 = (size_t)(b*SEQ + qblk*64 + wid*16 + (lane >> 2));
    size_t zb0 = tok0 * D_MODEL + h * D_HEAD + (lane & 3)*2;
    size_t zb1 = zb0 + (size_t)8 * D_MODEL;
#pragma unroll
    for (int nb = 0; nb < 8; nb++) {
        *(__half2*)(Z + zb0 + nb*8) = __floats2half2_rn(oacc[nb][0]*i0, oacc[nb][1]*i0);
        *(__half2*)(Z + zb1 + nb*8) = __floats2half2_rn(oacc[nb][2]*i1, oacc[nb][3]*i1);
    }
}

// ---------------------------------------------------------------------------
// launch
// ---------------------------------------------------------------------------
extern "C" void kernel_launch(void* const* d_in, const int* in_sizes, int n_in,
                              void* d_out, int out_size) {
    const float* resid_pre = (const float*)d_in[0];
    const float* ln1_w = (const float*)d_in[1];
    const float* ln1_b = (const float*)d_in[2];
    const float* W_Q   = (const float*)d_in[3];
    const float* b_Q   = (const float*)d_in[4];
    const float* W_K   = (const float*)d_in[5];
    const float* b_K   = (const float*)d_in[6];
    const float* W_V   = (const float*)d_in[7];
    const float* b_V   = (const float*)d_in[8];
    const float* W_O   = (const float*)d_in[9];
    const float* b_O   = (const float*)d_in[10];
    const float* ln2_w = (const float*)d_in[11];
    const float* ln2_b = (const float*)d_in[12];
    const float* W_in  = (const float*)d_in[13];
    const float* b_in  = (const float*)d_in[14];
    const float* W_out = (const float*)d_in[15];
    const float* b_out = (const float*)d_in[16];
    float* out = (float*)d_out;

    __half *p_ln1, *p_q, *p_k, *p_v, *p_z, *p_ln2, *p_mlp, *p_wqkv, *p_wo, *p_win, *p_wout;
    float *p_rmid;

    cudaGetSymbolAddress((void**)&p_ln1,  g_ln1);
    cudaGetSymbolAddress((void**)&p_q,    g_q);
    cudaGetSymbolAddress((void**)&p_k,    g_k);
    cudaGetSymbolAddress((void**)&p_v,    g_v);
    cudaGetSymbolAddress((void**)&p_z,    g_z);
    cudaGetSymbolAddress((void**)&p_rmid, g_rmid);
    cudaGetSymbolAddress((void**)&p_ln2,  g_ln2);
    cudaGetSymbolAddress((void**)&p_mlp,  g_mlp);
    cudaGetSymbolAddress((void**)&p_wqkv, g_wqkv);
    cudaGetSymbolAddress((void**)&p_wo,   g_wo);
    cudaGetSymbolAddress((void**)&p_win,  g_win);
    cudaGetSymbolAddress((void**)&p_wout, g_wout);

    cudaFuncSetAttribute(gemm_h<1,false>, cudaFuncAttributeMaxDynamicSharedMemorySize, GEMM_SMEM);
    cudaFuncSetAttribute(gemm_h<2,false>, cudaFuncAttributeMaxDynamicSharedMemorySize, GEMM_SMEM);
    cudaFuncSetAttribute(gemm_h<3,true >, cudaFuncAttributeMaxDynamicSharedMemorySize, GEMM_SMEM);

    // 1) ALL weight transposes in one launch
    transpose_all<<<3072, 256>>>(W_Q, W_K, W_V, W_O, W_in, W_out,
                                 p_wqkv, p_wo, p_win, p_wout);

    // 2) LN1 -> fp16
    ln_h_kernel<<<NTOK, 256>>>(resid_pre, ln1_w, ln1_b, p_ln1);

    // 3) fused QKV projection -> fp16 q,k,v (segment-select)
    dim3 gQKV(3*D_MODEL/128, NTOK/128);
    gemm_h<3,true><<<gQKV, 256, GEMM_SMEM>>>(p_ln1, p_wqkv, b_Q, b_K, b_V, nullptr,
                                             nullptr, p_q, p_k, p_v, NTOK, 3*D_MODEL, D_MODEL);

    // 4) HMMA flash attention -> fp16 z
    attn_hmma<<<dim3(SEQ/64, BATCH*N_HEADS), 128>>>(p_q, p_k, p_v, p_z);

    // 5) O projection + residual -> rmid (fp32)   [ncu -s 5 profiles this]
    dim3 gProj(D_MODEL/128, NTOK/128);
    gemm_h<1,false><<<gProj, 256, GEMM_SMEM>>>(p_z, p_wo, b_O, nullptr, nullptr, resid_pre,
                                               p_rmid, nullptr, nullptr, nullptr, NTOK, D_MODEL, D_MODEL);

    // 6) LN2 -> fp16
    ln_h_kernel<<<NTOK, 256>>>(p_rmid, ln2_w, ln2_b, p_ln2);

    // 7) MLP in + ReLU -> fp16
    dim3 gMlp1(D_MLP/128, NTOK/128);
    gemm_h<2,false><<<gMlp1, 256, GEMM_SMEM>>>(p_ln2, p_win, b_in, nullptr, nullptr, nullptr,
                                               nullptr, p_mlp, nullptr, nullptr, NTOK, D_MLP, D_MODEL);

    // 8) MLP out + residual -> output (fp32)
    gemm_h<1,false><<<gProj, 256, GEMM_SMEM>>>(p_mlp, p_wout, b_out, nullptr, nullptr, p_rmid,
                                               out, nullptr, nullptr, nullptr, NTOK, D_MODEL, D_MLP);
}

// round 13
// speedup vs baseline: 1.4355x; 1.4355x over previous
#include <cuda_runtime.h>
#include <cuda_fp16.h>
#include <math.h>
#include <stdint.h>

#define D_MODEL 1024
#define N_HEADS 16
#define D_HEAD  64
#define D_MLP   4096
#define BATCH   2
#define SEQ     2048
#define NTOK    (BATCH*SEQ)   // 4096
#define LN_EPS  1e-5f

// ---------------------------------------------------------------------------
// scratch (static device globals; no allocation)
// ---------------------------------------------------------------------------
__device__ __half g_ln1[NTOK*D_MODEL];
__device__ __half g_q  [NTOK*D_MODEL];
__device__ __half g_k  [NTOK*D_MODEL];
__device__ __half g_v  [NTOK*D_MODEL];
__device__ __half g_z  [NTOK*D_MODEL];
__device__ float  g_rmid[NTOK*D_MODEL];
__device__ __half g_ln2[NTOK*D_MODEL];
__device__ __half g_mlp[(size_t)NTOK*D_MLP];
// transposed fp16 weights ([N,K] row-major, k-contiguous)
__device__ __half g_wqkv[3*D_MODEL*D_MODEL];     // rows 0..1023 Q, 1024..2047 K, 2048..3071 V
__device__ __half g_wo  [D_MODEL*D_MODEL];
__device__ __half g_win [(size_t)D_MLP*D_MODEL];
__device__ __half g_wout[(size_t)D_MODEL*D_MLP];

// ---------------------------------------------------------------------------
// helpers
// ---------------------------------------------------------------------------
__device__ __forceinline__ uint32_t smem_to_u32(const void* p) {
    uint32_t a;
    asm("{ .reg .u64 t; cvta.to.shared.u64 t, %1; cvt.u32.u64 %0, t; }" : "=r"(a) : "l"(p));
    return a;
}
__device__ __forceinline__ void cp16(uint32_t s, const void* g) {
    asm volatile("cp.async.cg.shared.global [%0], [%1], 16;" :: "r"(s), "l"(g));
}
__device__ __forceinline__ void ldmx4(uint32_t* r, uint32_t addr) {
    asm volatile("ldmatrix.sync.aligned.m8n8.x4.shared.b16 {%0,%1,%2,%3}, [%4];"
        : "=r"(r[0]), "=r"(r[1]), "=r"(r[2]), "=r"(r[3]) : "r"(addr));
}
__device__ __forceinline__ void ldmx4t(uint32_t* r, uint32_t addr) {
    asm volatile("ldmatrix.sync.aligned.m8n8.x4.trans.shared.b16 {%0,%1,%2,%3}, [%4];"
        : "=r"(r[0]), "=r"(r[1]), "=r"(r[2]), "=r"(r[3]) : "r"(addr));
}
__device__ __forceinline__ void mma16816(float* d, const uint32_t* a, uint32_t b0, uint32_t b1) {
    asm volatile("mma.sync.aligned.m16n8k16.row.col.f32.f16.f16.f32 "
        "{%0,%1,%2,%3}, {%4,%5,%6,%7}, {%8,%9}, {%0,%1,%2,%3};"
        : "+f"(d[0]), "+f"(d[1]), "+f"(d[2]), "+f"(d[3])
        : "r"(a[0]), "r"(a[1]), "r"(a[2]), "r"(a[3]), "r"(b0), "r"(b1));
}
__device__ __forceinline__ uint32_t packh2(float x, float y) {
    __half2 h = __floats2half2_rn(x, y);
    return *(uint32_t*)&h;
}

// ---------------------------------------------------------------------------
// merged weight transpose: ALL weights in one launch (3072 blocks).
// ---------------------------------------------------------------------------
__global__ void transpose_all(const float* __restrict__ WQ, const float* __restrict__ WK,
                              const float* __restrict__ WV, const float* __restrict__ WO,
                              const float* __restrict__ Win, const float* __restrict__ Wout,
                              __half* __restrict__ wqkv, __half* __restrict__ wo,
                              __half* __restrict__ win, __half* __restrict__ wout) {
    __shared__ float t[64][65];
    const int bid = blockIdx.x;
    const float* src; __half* dst;
    int K, N, n0, k0;
    if (bid < 768) {
        int z = bid >> 4, kt = bid & 15;
        int seg = z >> 4, head = z & 15;
        src = (seg == 0 ? WQ : seg == 1 ? WK : WV) + (size_t)head * 1024 * 64;
        dst = wqkv + (size_t)seg * 1024 * 1024 + (size_t)head * 64 * 1024;
        K = 1024; N = 64; n0 = 0; k0 = kt * 64;
    } else if (bid < 1024) {
        int tt = bid - 768; n0 = (tt & 15) * 64; k0 = (tt >> 4) * 64;
        src = WO; dst = wo; K = 1024; N = 1024;
    } else if (bid < 2048) {
        int tt = bid - 1024; n0 = (tt & 63) * 64; k0 = (tt >> 6) * 64;
        src = Win; dst = win; K = 1024; N = 4096;
    } else {
        int tt = bid - 2048; n0 = (tt & 15) * 64; k0 = (tt >> 4) * 64;
        src = Wout; dst = wout; K = 4096; N = 1024;
    }
    const int tid = threadIdx.x;
    {
        int c4 = tid & 15, r = tid >> 4;
#pragma unroll
        for (int i = 0; i < 4; i++) {
            float4 v = *(const float4*)(src + (size_t)(k0 + r + i*16) * N + n0 + c4*4);
            t[r + i*16][c4*4+0] = v.x;
            t[r + i*16][c4*4+1] = v.y;
            t[r + i*16][c4*4+2] = v.z;
            t[r + i*16][c4*4+3] = v.w;
        }
    }
    __syncthreads();
    {
        int kg = (tid & 7) * 8;
#pragma unroll
        for (int p = 0; p < 2; p++) {
            int n = (tid >> 3) + p*32;
            __half h[8];
#pragma unroll
            for (int q = 0; q < 8; q++) h[q] = __float2half_rn(t[kg + q][n]);
            *(uint4*)(dst + (size_t)(n0 + n) * K + k0 + kg) = *(uint4*)h;
        }
    }
}

// ---------------------------------------------------------------------------
// LayerNorm -> fp16
// ---------------------------------------------------------------------------
__global__ void ln_h_kernel(const float* __restrict__ x, const float* __restrict__ w,
                            const float* __restrict__ b, __half* __restrict__ o) {
    int row = blockIdx.x;
    const float* xr = x + (size_t)row * D_MODEL;
    float vals[4];
    float s = 0.f, s2 = 0.f;
#pragma unroll
    for (int i = 0; i < 4; i++) {
        float v = xr[threadIdx.x + i*256];
        vals[i] = v; s += v; s2 += v*v;
    }
#pragma unroll
    for (int off = 16; off > 0; off >>= 1) {
        s  += __shfl_xor_sync(0xFFFFFFFFu, s,  off);
        s2 += __shfl_xor_sync(0xFFFFFFFFu, s2, off);
    }
    __shared__ float sh[2][8];
    int wid = threadIdx.x >> 5, lid = threadIdx.x & 31;
    if (lid == 0) { sh[0][wid] = s; sh[1][wid] = s2; }
    __syncthreads();
    s = 0.f; s2 = 0.f;
#pragma unroll
    for (int i = 0; i < 8; i++) { s += sh[0][i]; s2 += sh[1][i]; }
    float mean = s * (1.f/(float)D_MODEL);
    float var  = s2 * (1.f/(float)D_MODEL) - mean*mean;
    float rstd = rsqrtf(var + LN_EPS);
#pragma unroll
    for (int i = 0; i < 4; i++) {
        int c = threadIdx.x + i*256;
        float v = (vals[i] - mean) * rstd * w[c] + b[c];
        o[(size_t)row * D_MODEL + c] = __float2half_rn(v);
    }
}

// ---------------------------------------------------------------------------
// fp16 HMMA GEMM (round-9 proven shape): C[M,N] = A[M,K] @ B^T  (B [N,K] fp16)
// CTA tile 128x128, BK=32, 256 threads (8 warps 2x4, 64x32/warp),
// 3-stage cp.async pipeline, ONE __syncthreads per k-iteration, 2 CTAs/SM.
// ---------------------------------------------------------------------------
#define TILE_B    10240              // 128 rows * 80 bytes
#define STAGE_B   (2*TILE_B)         // A + B tiles
#define NSTAGE    3
#define GEMM_SMEM (NSTAGE*STAGE_B)   // 61440

template<int MODE, bool SEG>
__global__ void __launch_bounds__(256, 2) gemm_h(
    const __half* __restrict__ A, const __half* __restrict__ B,
    const float* __restrict__ b0, const float* __restrict__ b1, const float* __restrict__ b2,
    const float* __restrict__ res,
    float* __restrict__ C0,
    __half* __restrict__ Ch0, __half* __restrict__ Ch1, __half* __restrict__ Ch2,
    int M, int N, int K)
{
    extern __shared__ __align__(128) char smem[];
    const uint32_t sbase = smem_to_u32(smem);
    const int tid  = threadIdx.x;
    const int lane = tid & 31;
    const int wid  = tid >> 5;
    const int wm   = wid >> 2;
    const int wn   = wid & 3;
    const int bm   = blockIdx.y * 128;
    const int bn   = blockIdx.x * 128;

    const float* bias = b0;
    __half* Chx = Ch0;
    int bnl = bn, ldc = N;
    if (SEG) {
        int sg = bn >> 10;
        bias = (sg == 0) ? b0 : (sg == 1) ? b1 : b2;
        Chx  = (sg == 0) ? Ch0 : (sg == 1) ? Ch1 : Ch2;
        bnl  = bn & 1023;
        ldc  = 1024;
    }

    float acc[4][4][4];
#pragma unroll
    for (int i = 0; i < 4; i++)
#pragma unroll
        for (int j = 0; j < 4; j++)
#pragma unroll
            for (int q = 0; q < 4; q++) acc[i][j][q] = 0.f;

    const int nk = K >> 5;

    auto load_stage = [&](int kt, int buf) {
        const int k0 = kt << 5;
        const uint32_t sb0 = sbase + buf * STAGE_B;
#pragma unroll
        for (int u = 0; u < 2; u++) {
            int f   = tid + u * 256;
            int row = f >> 2, c = f & 3;
            uint32_t soff = (uint32_t)(row * 80 + c * 16);
            cp16(sb0 + 0*TILE_B + soff, A + (size_t)(bm + row) * K + k0 + c * 8);
            cp16(sb0 + 1*TILE_B + soff, B + (size_t)(bn + row) * K + k0 + c * 8);
        }
    };

    const uint32_t aRowOff = (uint32_t)((wm*64 + (lane & 15)) * 80 + (lane >> 4) * 16);
    const uint32_t bRowOff = (uint32_t)((wn*32 + (lane & 15)) * 80 + (lane >> 4) * 16);

    load_stage(0, 0);
    asm volatile("cp.async.commit_group;");
    load_stage(1, 1);
    asm volatile("cp.async.commit_group;");

    for (int kt = 0; kt < nk; kt++) {
        if (kt < nk - 1) asm volatile("cp.async.wait_group 1;" ::: "memory");
        else             asm volatile("cp.async.wait_group 0;" ::: "memory");
        __syncthreads();

        const uint32_t sb0 = sbase + (uint32_t)(kt % NSTAGE) * STAGE_B;
#pragma unroll
        for (int ks = 0; ks < 2; ks++) {
            const uint32_t koff = ks * 32;
            uint32_t a[4][4], bb[2][4];
#pragma unroll
            for (int i = 0; i < 4; i++)
                ldmx4(a[i], sb0 + 0*TILE_B + aRowOff + (uint32_t)(i*16*80) + koff);
#pragma unroll
            for (int j = 0; j < 2; j++)
                ldmx4(bb[j], sb0 + 1*TILE_B + bRowOff + (uint32_t)(j*16*80) + koff);
#pragma unroll
            for (int i = 0; i < 4; i++)
#pragma unroll
                for (int nb = 0; nb < 4; nb++) {
                    int j = nb >> 1, sel = nb & 1;
                    mma16816(acc[i][nb], a[i], bb[j][sel], bb[j][sel + 2]);
                }
        }

        if (kt + 2 < nk) {
            load_stage(kt + 2, (kt + 2) % NSTAGE);
            asm volatile("cp.async.commit_group;");
        }
    }

    // --- epilogue ---
    const int mrow = bm + wm*64 + (lane >> 2);
    const int ncol = bnl + wn*32 + (lane & 3) * 2;
#pragma unroll
    for (int i = 0; i < 4; i++) {
#pragma unroll
        for (int jj = 0; jj < 4; jj++) {
            int r0 = mrow + i*16;
            int c  = ncol + jj*8;
            float2 bv = *(const float2*)(bias + c);
            float x0 = acc[i][jj][0] + bv.x;
            float x1 = acc[i][jj][1] + bv.y;
            float x2 = acc[i][jj][2] + bv.x;
            float x3 = acc[i][jj][3] + bv.y;
            if (MODE == 2) {
                x0 = fmaxf(x0, 0.f); x1 = fmaxf(x1, 0.f);
                x2 = fmaxf(x2, 0.f); x3 = fmaxf(x3, 0.f);
                *(__half2*)(Chx + (size_t)r0 * ldc + c)     = __floats2half2_rn(x0, x1);
                *(__half2*)(Chx + (size_t)(r0+8) * ldc + c) = __floats2half2_rn(x2, x3);
            } else if (MODE == 3) {
                *(__half2*)(Chx + (size_t)r0 * ldc + c)     = __floats2half2_rn(x0, x1);
                *(__half2*)(Chx + (size_t)(r0+8) * ldc + c) = __floats2half2_rn(x2, x3);
            } else {
                float2 rv0 = *(const float2*)(res + (size_t)r0 * ldc + c);
                float2 rv1 = *(const float2*)(res + (size_t)(r0+8) * ldc + c);
                x0 += rv0.x; x1 += rv0.y; x2 += rv1.x; x3 += rv1.y;
                *(float2*)(C0 + (size_t)r0 * ldc + c)     = make_float2(x0, x1);
                *(float2*)(C0 + (size_t)(r0+8) * ldc + c) = make_float2(x2, x3);
            }
        }
    }
}

// ---------------------------------------------------------------------------
// HMMA flash attention (fp16 in, fp32 accum, causal) -> fp16 z
// CTA: 128 q-rows x one (b,h); 8 warps, 16 q-rows/warp; KV tiles of 64,
// cp.async double buffer. Halves K/V traffic vs 64-row version.
// ---------------------------------------------------------------------------
__global__ void __launch_bounds__(256) attn_hmma(
    const __half* __restrict__ Q, const __half* __restrict__ K,
    const __half* __restrict__ V, __half* __restrict__ Z)
{
    __shared__ __align__(16) __half sQ[128*72];
    __shared__ __align__(16) __half sK[2][64*72];
    __shared__ __align__(16) __half sV[2][64*72];
    const int tid = threadIdx.x, lane = tid & 31, wid = tid >> 5;
    const int qb = (SEQ/128 - 1) - blockIdx.x;      // heavy blocks first
    const int bh = blockIdx.y, b = bh >> 4, h = bh & 15;
    const uint32_t uQ = smem_to_u32(sQ);
    const uint32_t uK = smem_to_u32(sK);
    const uint32_t uV = smem_to_u32(sV);
    const size_t qbase = ((size_t)(b*SEQ + qb*128)) * D_MODEL + h * D_HEAD;

    // Q: 128 rows x 8 chunks = 1024
    for (int f = tid; f < 1024; f += 256) {
        int row = f >> 3, c = f & 7;
        cp16(uQ + row*144 + c*16, Q + qbase + (size_t)row * D_MODEL + c*8);
    }
    auto load_kv = [&](int kt, int buf) {
        size_t base = ((size_t)(b*SEQ + kt*64)) * D_MODEL + h * D_HEAD;
        for (int f = tid; f < 512; f += 256) {
            int row = f >> 3, c = f & 7;
            cp16(uK + buf*(64*144) + row*144 + c*16, K + base + (size_t)row * D_MODEL + c*8);
            cp16(uV + buf*(64*144) + row*144 + c*16, V + base + (size_t)row * D_MODEL + c*8);
        }
    };
    load_kv(0, 0);
    asm volatile("cp.async.commit_group;");

    float oacc[8][4];
#pragma unroll
    for (int i = 0; i < 8; i++)
#pragma unroll
        for (int c = 0; c < 4; c++) oacc[i][c] = 0.f;
    float m0 = -INFINITY, m1 = -INFINITY, l0 = 0.f, l1 = 0.f;
    uint32_t a[4][4];

    const int ntiles = 2*qb + 2;
    const int qwarp0 = qb*128 + wid*16;             // warp's first global q row
    for (int kt = 0; kt < ntiles; kt++) {
        if (kt + 1 < ntiles) {
            load_kv(kt + 1, (kt + 1) & 1);
            asm volatile("cp.async.commit_group;");
            asm volatile("cp.async.wait_group 1;");
        } else {
            asm volatile("cp.async.wait_group 0;");
        }
        __syncthreads();

        if (kt == 0) {
#pragma unroll
            for (int kk = 0; kk < 4; kk++)
                ldmx4(a[kk], uQ + (uint32_t)((wid*16 + (lane & 15))*144 + kk*32 + (lane >> 4)*16));
        }

        // S = Q K^T
        const uint32_t kb0 = uK + (uint32_t)((kt & 1) * (64*144));
        float sc[8][4];
#pragma unroll
        for (int i = 0; i < 8; i++)
#pragma unroll
            for (int c = 0; c < 4; c++) sc[i][c] = 0.f;
#pragma unroll
        for (int kk = 0; kk < 4; kk++) {
            uint32_t kb[4][4];
#pragma unroll
            for (int j = 0; j < 4; j++)
                ldmx4(kb[j], kb0 + (uint32_t)((j*16 + (lane & 15))*144 + kk*32 + (lane >> 4)*16));
#pragma unroll
            for (int j = 0; j < 4; j++) {
                mma16816(sc[2*j],   a[kk], kb[j][0], kb[j][2]);
                mma16816(sc[2*j+1], a[kk], kb[j][1], kb[j][3]);
            }
        }

        // softmax (online), global-index causal mask
        const float scale = 0.125f;   // 1/sqrt(64)
        const bool diag = (kt*64 + 63) > qwarp0;    // tile may touch this warp's causal edge
        const int qg0 = qwarp0 + (lane >> 2);
        float mx0 = m0, mx1 = m1;
#pragma unroll
        for (int nb = 0; nb < 8; nb++) {
#pragma unroll
            for (int c = 0; c < 4; c++) {
                float s = sc[nb][c] * scale;
                if (diag) {
                    int jg = kt*64 + nb*8 + (lane & 3)*2 + (c & 1);
                    int qg = qg0 + ((c >> 1) << 3);
                    if (jg > qg) s = -INFINITY;
                }
                sc[nb][c] = s;
            }
            mx0 = fmaxf(mx0, fmaxf(sc[nb][0], sc[nb][1]));
            mx1 = fmaxf(mx1, fmaxf(sc[nb][2], sc[nb][3]));
        }
        mx0 = fmaxf(mx0, __shfl_xor_sync(0xFFFFFFFFu, mx0, 1));
        mx0 = fmaxf(mx0, __shfl_xor_sync(0xFFFFFFFFu, mx0, 2));
        mx1 = fmaxf(mx1, __shfl_xor_sync(0xFFFFFFFFu, mx1, 1));
        mx1 = fmaxf(mx1, __shfl_xor_sync(0xFFFFFFFFu, mx1, 2));
        float fac0 = __expf(m0 - mx0), fac1 = __expf(m1 - mx1);
        m0 = mx0; m1 = mx1;
        float ls0 = 0.f, ls1 = 0.f;
#pragma unroll
        for (int nb = 0; nb < 8; nb++) {
            sc[nb][0] = __expf(sc[nb][0] - mx0);
            sc[nb][1] = __expf(sc[nb][1] - mx0);
            sc[nb][2] = __expf(sc[nb][2] - mx1);
            sc[nb][3] = __expf(sc[nb][3] - mx1);
            ls0 += sc[nb][0] + sc[nb][1];
            ls1 += sc[nb][2] + sc[nb][3];
        }
        l0 = l0 * fac0 + ls0;
        l1 = l1 * fac1 + ls1;
#pragma unroll
        for (int nb = 0; nb < 8; nb++) {
            oacc[nb][0] *= fac0; oacc[nb][1] *= fac0;
            oacc[nb][2] *= fac1; oacc[nb][3] *= fac1;
        }

        // O += P V
        const uint32_t vb0 = uV + (uint32_t)((kt & 1) * (64*144));
#pragma unroll
        for (int kk = 0; kk < 4; kk++) {
            uint32_t pa[4];
            pa[0] = packh2(sc[2*kk][0],   sc[2*kk][1]);
            pa[1] = packh2(sc[2*kk][2],   sc[2*kk][3]);
            pa[2] = packh2(sc[2*kk+1][0], sc[2*kk+1][1]);
            pa[3] = packh2(sc[2*kk+1][2], sc[2*kk+1][3]);
#pragma unroll
            for (int j = 0; j < 4; j++) {
                uint32_t vb[4];
                ldmx4t(vb, vb0 + (uint32_t)((kk*16 + (lane & 15))*144 + j*32 + (lane >> 4)*16));
                mma16816(oacc[2*j],   pa, vb[0], vb[1]);
                mma16816(oacc[2*j+1], pa, vb[2], vb[3]);
            }
        }
        __syncthreads();
    }

    // normalize + store
    l0 += __shfl_xor_sync(0xFFFFFFFFu, l0, 1);
    l0 += __shfl_xor_sync(0xFFFFFFFFu, l0, 2);
    l1 += __shfl_xor_sync(0xFFFFFFFFu, l1, 1);
    l1 += __shfl_xor_sync(0xFFFFFFFFu, l1, 2);
    float i0 = 1.f / l0, i1 = 1.f / l1;
    size_t tok0 = (size_t)(b*SEQ + qb*128 + wid*16 + (lane >> 2));
    size_t zb0 = tok0 * D_MODEL + h * D_HEAD + (lane & 3)*2;
    size_t zb1 = zb0 + (size_t)8 * D_MODEL;
#pragma unroll
    for (int nb = 0; nb < 8; nb++) {
        *(__half2*)(Z + zb0 + nb*8) = __floats2half2_rn(oacc[nb][0]*i0, oacc[nb][1]*i0);
        *(__half2*)(Z + zb1 + nb*8) = __floats2half2_rn(oacc[nb][2]*i1, oacc[nb][3]*i1);
    }
}

// ---------------------------------------------------------------------------
// launch
// ---------------------------------------------------------------------------
extern "C" void kernel_launch(void* const* d_in, const int* in_sizes, int n_in,
                              void* d_out, int out_size) {
    const float* resid_pre = (const float*)d_in[0];
    const float* ln1_w = (const float*)d_in[1];
    const float* ln1_b = (const float*)d_in[2];
    const float* W_Q   = (const float*)d_in[3];
    const float* b_Q   = (const float*)d_in[4];
    const float* W_K   = (const float*)d_in[5];
    const float* b_K   = (const float*)d_in[6];
    const float* W_V   = (const float*)d_in[7];
    const float* b_V   = (const float*)d_in[8];
    const float* W_O   = (const float*)d_in[9];
    const float* b_O   = (const float*)d_in[10];
    const float* ln2_w = (const float*)d_in[11];
    const float* ln2_b = (const float*)d_in[12];
    const float* W_in  = (const float*)d_in[13];
    const float* b_in  = (const float*)d_in[14];
    const float* W_out = (const float*)d_in[15];
    const float* b_out = (const float*)d_in[16];
    float* out = (float*)d_out;

    __half *p_ln1, *p_q, *p_k, *p_v, *p_z, *p_ln2, *p_mlp, *p_wqkv, *p_wo, *p_win, *p_wout;
    float *p_rmid;

    cudaGetSymbolAddress((void**)&p_ln1,  g_ln1);
    cudaGetSymbolAddress((void**)&p_q,    g_q);
    cudaGetSymbolAddress((void**)&p_k,    g_k);
    cudaGetSymbolAddress((void**)&p_v,    g_v);
    cudaGetSymbolAddress((void**)&p_z,    g_z);
    cudaGetSymbolAddress((void**)&p_rmid, g_rmid);
    cudaGetSymbolAddress((void**)&p_ln2,  g_ln2);
    cudaGetSymbolAddress((void**)&p_mlp,  g_mlp);
    cudaGetSymbolAddress((void**)&p_wqkv, g_wqkv);
    cudaGetSymbolAddress((void**)&p_wo,   g_wo);
    cudaGetSymbolAddress((void**)&p_win,  g_win);
    cudaGetSymbolAddress((void**)&p_wout, g_wout);

    cudaFuncSetAttribute(gemm_h<1,false>, cudaFuncAttributeMaxDynamicSharedMemorySize, GEMM_SMEM);
    cudaFuncSetAttribute(gemm_h<2,false>, cudaFuncAttributeMaxDynamicSharedMemorySize, GEMM_SMEM);
    cudaFuncSetAttribute(gemm_h<3,true >, cudaFuncAttributeMaxDynamicSharedMemorySize, GEMM_SMEM);

    // 1) ALL weight transposes in one launch
    transpose_all<<<3072, 256>>>(W_Q, W_K, W_V, W_O, W_in, W_out,
                                 p_wqkv, p_wo, p_win, p_wout);

    // 2) LN1 -> fp16
    ln_h_kernel<<<NTOK, 256>>>(resid_pre, ln1_w, ln1_b, p_ln1);

    // 3) fused QKV projection -> fp16 q,k,v (segment-select)
    dim3 gQKV(3*D_MODEL/128, NTOK/128);
    gemm_h<3,true><<<gQKV, 256, GEMM_SMEM>>>(p_ln1, p_wqkv, b_Q, b_K, b_V, nullptr,
                                             nullptr, p_q, p_k, p_v, NTOK, 3*D_MODEL, D_MODEL);

    // 4) HMMA flash attention (128 q-rows/CTA) -> fp16 z
    attn_hmma<<<dim3(SEQ/128, BATCH*N_HEADS), 256>>>(p_q, p_k, p_v, p_z);

    // 5) O projection + residual -> rmid (fp32)
    dim3 gProj(D_MODEL/128, NTOK/128);
    gemm_h<1,false><<<gProj, 256, GEMM_SMEM>>>(p_z, p_wo, b_O, nullptr, nullptr, resid_pre,
                                               p_rmid, nullptr, nullptr, nullptr, NTOK, D_MODEL, D_MODEL);

    // 6) LN2 -> fp16
    ln_h_kernel<<<NTOK, 256>>>(p_rmid, ln2_w, ln2_b, p_ln2);

    // 7) MLP in + ReLU -> fp16
    dim3 gMlp1(D_MLP/128, NTOK/128);
    gemm_h<2,false><<<gMlp1, 256, GEMM_SMEM>>>(p_ln2, p_win, b_in, nullptr, nullptr, nullptr,
                                               nullptr, p_mlp, nullptr, nullptr, NTOK, D_MLP, D_MODEL);

    // 8) MLP out + residual -> output (fp32)
    gemm_h<1,false><<<gProj, 256, GEMM_SMEM>>>(p_mlp, p_wout, b_out, nullptr, nullptr, p_rmid,
                                               out, nullptr, nullptr, nullptr, NTOK, D_MODEL, D_MLP);
}

// round 14
// speedup vs baseline: 1.5364x; 1.0703x over previous
#include <cuda_runtime.h>
#include <cuda_fp16.h>
#include <math.h>
#include <stdint.h>

#define D_MODEL 1024
#define N_HEADS 16
#define D_HEAD  64
#define D_MLP   4096
#define BATCH   2
#define SEQ     2048
#define NTOK    (BATCH*SEQ)   // 4096
#define LN_EPS  1e-5f

// ---------------------------------------------------------------------------
// scratch (static device globals; no allocation)
// ---------------------------------------------------------------------------
__device__ __half g_ln1[NTOK*D_MODEL];
__device__ __half g_q  [NTOK*D_MODEL];
__device__ __half g_k  [NTOK*D_MODEL];
__device__ __half g_v  [NTOK*D_MODEL];
__device__ __half g_z  [NTOK*D_MODEL];
__device__ float  g_rmid[NTOK*D_MODEL];
__device__ __half g_ln2[NTOK*D_MODEL];
__device__ __half g_mlp[(size_t)NTOK*D_MLP];
// transposed fp16 weights ([N,K] row-major, k-contiguous)
__device__ __half g_wqkv[3*D_MODEL*D_MODEL];     // rows 0..1023 Q, 1024..2047 K, 2048..3071 V
__device__ __half g_wo  [D_MODEL*D_MODEL];
__device__ __half g_win [(size_t)D_MLP*D_MODEL];
__device__ __half g_wout[(size_t)D_MODEL*D_MLP];

// ---------------------------------------------------------------------------
// helpers
// ---------------------------------------------------------------------------
__device__ __forceinline__ uint32_t smem_to_u32(const void* p) {
    uint32_t a;
    asm("{ .reg .u64 t; cvta.to.shared.u64 t, %1; cvt.u32.u64 %0, t; }" : "=r"(a) : "l"(p));
    return a;
}
__device__ __forceinline__ void cp16(uint32_t s, const void* g) {
    asm volatile("cp.async.cg.shared.global [%0], [%1], 16;" :: "r"(s), "l"(g));
}
__device__ __forceinline__ void ldmx4(uint32_t* r, uint32_t addr) {
    asm volatile("ldmatrix.sync.aligned.m8n8.x4.shared.b16 {%0,%1,%2,%3}, [%4];"
        : "=r"(r[0]), "=r"(r[1]), "=r"(r[2]), "=r"(r[3]) : "r"(addr));
}
__device__ __forceinline__ void ldmx4t(uint32_t* r, uint32_t addr) {
    asm volatile("ldmatrix.sync.aligned.m8n8.x4.trans.shared.b16 {%0,%1,%2,%3}, [%4];"
        : "=r"(r[0]), "=r"(r[1]), "=r"(r[2]), "=r"(r[3]) : "r"(addr));
}
__device__ __forceinline__ void mma16816(float* d, const uint32_t* a, uint32_t b0, uint32_t b1) {
    asm volatile("mma.sync.aligned.m16n8k16.row.col.f32.f16.f16.f32 "
        "{%0,%1,%2,%3}, {%4,%5,%6,%7}, {%8,%9}, {%0,%1,%2,%3};"
        : "+f"(d[0]), "+f"(d[1]), "+f"(d[2]), "+f"(d[3])
        : "r"(a[0]), "r"(a[1]), "r"(a[2]), "r"(a[3]), "r"(b0), "r"(b1));
}
__device__ __forceinline__ uint32_t packh2(float x, float y) {
    __half2 h = __floats2half2_rn(x, y);
    return *(uint32_t*)&h;
}

// ---------------------------------------------------------------------------
// merged weight transpose: ALL weights in one launch (3072 blocks).
// ---------------------------------------------------------------------------
__global__ void transpose_all(const float* __restrict__ WQ, const float* __restrict__ WK,
                              const float* __restrict__ WV, const float* __restrict__ WO,
                              const float* __restrict__ Win, const float* __restrict__ Wout,
                              __half* __restrict__ wqkv, __half* __restrict__ wo,
                              __half* __restrict__ win, __half* __restrict__ wout) {
    __shared__ float t[64][65];
    const int bid = blockIdx.x;
    const float* src; __half* dst;
    int K, N, n0, k0;
    if (bid < 768) {
        int z = bid >> 4, kt = bid & 15;
        int seg = z >> 4, head = z & 15;
        src = (seg == 0 ? WQ : seg == 1 ? WK : WV) + (size_t)head * 1024 * 64;
        dst = wqkv + (size_t)seg * 1024 * 1024 + (size_t)head * 64 * 1024;
        K = 1024; N = 64; n0 = 0; k0 = kt * 64;
    } else if (bid < 1024) {
        int tt = bid - 768; n0 = (tt & 15) * 64; k0 = (tt >> 4) * 64;
        src = WO; dst = wo; K = 1024; N = 1024;
    } else if (bid < 2048) {
        int tt = bid - 1024; n0 = (tt & 63) * 64; k0 = (tt >> 6) * 64;
        src = Win; dst = win; K = 1024; N = 4096;
    } else {
        int tt = bid - 2048; n0 = (tt & 15) * 64; k0 = (tt >> 4) * 64;
        src = Wout; dst = wout; K = 4096; N = 1024;
    }
    const int tid = threadIdx.x;
    {
        int c4 = tid & 15, r = tid >> 4;
#pragma unroll
        for (int i = 0; i < 4; i++) {
            float4 v = *(const float4*)(src + (size_t)(k0 + r + i*16) * N + n0 + c4*4);
            t[r + i*16][c4*4+0] = v.x;
            t[r + i*16][c4*4+1] = v.y;
            t[r + i*16][c4*4+2] = v.z;
            t[r + i*16][c4*4+3] = v.w;
        }
    }
    __syncthreads();
    {
        int kg = (tid & 7) * 8;
#pragma unroll
        for (int p = 0; p < 2; p++) {
            int n = (tid >> 3) + p*32;
            __half h[8];
#pragma unroll
            for (int q = 0; q < 8; q++) h[q] = __float2half_rn(t[kg + q][n]);
            *(uint4*)(dst + (size_t)(n0 + n) * K + k0 + kg) = *(uint4*)h;
        }
    }
}

// ---------------------------------------------------------------------------
// LayerNorm -> fp16
// ---------------------------------------------------------------------------
__global__ void ln_h_kernel(const float* __restrict__ x, const float* __restrict__ w,
                            const float* __restrict__ b, __half* __restrict__ o) {
    int row = blockIdx.x;
    const float* xr = x + (size_t)row * D_MODEL;
    float vals[4];
    float s = 0.f, s2 = 0.f;
#pragma unroll
    for (int i = 0; i < 4; i++) {
        float v = xr[threadIdx.x + i*256];
        vals[i] = v; s += v; s2 += v*v;
    }
#pragma unroll
    for (int off = 16; off > 0; off >>= 1) {
        s  += __shfl_xor_sync(0xFFFFFFFFu, s,  off);
        s2 += __shfl_xor_sync(0xFFFFFFFFu, s2, off);
    }
    __shared__ float sh[2][8];
    int wid = threadIdx.x >> 5, lid = threadIdx.x & 31;
    if (lid == 0) { sh[0][wid] = s; sh[1][wid] = s2; }
    __syncthreads();
    s = 0.f; s2 = 0.f;
#pragma unroll
    for (int i = 0; i < 8; i++) { s += sh[0][i]; s2 += sh[1][i]; }
    float mean = s * (1.f/(float)D_MODEL);
    float var  = s2 * (1.f/(float)D_MODEL) - mean*mean;
    float rstd = rsqrtf(var + LN_EPS);
#pragma unroll
    for (int i = 0; i < 4; i++) {
        int c = threadIdx.x + i*256;
        float v = (vals[i] - mean) * rstd * w[c] + b[c];
        o[(size_t)row * D_MODEL + c] = __float2half_rn(v);
    }
}

// ---------------------------------------------------------------------------
// fp16 HMMA GEMM: C[M,N] = A[M,K] @ B^T  (B stored [N,K] fp16)
// CTA tile 128x128, BK=64, 256 threads (8 warps 2x4, 64x32/warp),
// 3-stage cp.async pipeline (round-9 structure), ONE sync per k-iter (16 for
// K=1024), 2 CTAs/SM (216 KB smem/SM). 144B rows: ldmatrix conflict-free.
// MODE 1: fp32 C0 = acc + bias + res
// MODE 2: fp16 Ch0 = relu(acc + bias)
// MODE 3: fp16 Ch{0,1,2} = acc + bias   (SEG: segment-select by bn>>10, ldc=1024)
// ---------------------------------------------------------------------------
#define TILE_B    18432              // 128 rows * 144 bytes
#define STAGE_B   (2*TILE_B)         // A + B tiles
#define NSTAGE    3
#define GEMM_SMEM (NSTAGE*STAGE_B)   // 110592

template<int MODE, bool SEG>
__global__ void __launch_bounds__(256, 2) gemm_h(
    const __half* __restrict__ A, const __half* __restrict__ B,
    const float* __restrict__ b0, const float* __restrict__ b1, const float* __restrict__ b2,
    const float* __restrict__ res,
    float* __restrict__ C0,
    __half* __restrict__ Ch0, __half* __restrict__ Ch1, __half* __restrict__ Ch2,
    int M, int N, int K)
{
    extern __shared__ __align__(128) char smem[];
    const uint32_t sbase = smem_to_u32(smem);
    const int tid  = threadIdx.x;
    const int lane = tid & 31;
    const int wid  = tid >> 5;
    const int wm   = wid >> 2;
    const int wn   = wid & 3;
    const int bm   = blockIdx.y * 128;
    const int bn   = blockIdx.x * 128;

    const float* bias = b0;
    __half* Chx = Ch0;
    int bnl = bn, ldc = N;
    if (SEG) {
        int sg = bn >> 10;
        bias = (sg == 0) ? b0 : (sg == 1) ? b1 : b2;
        Chx  = (sg == 0) ? Ch0 : (sg == 1) ? Ch1 : Ch2;
        bnl  = bn & 1023;
        ldc  = 1024;
    }

    float acc[4][4][4];
#pragma unroll
    for (int i = 0; i < 4; i++)
#pragma unroll
        for (int j = 0; j < 4; j++)
#pragma unroll
            for (int q = 0; q < 4; q++) acc[i][j][q] = 0.f;

    const int nk = K >> 6;   // BK = 64  (K>=1024 -> nk>=16 > NSTAGE)

    auto load_stage = [&](int kt, int buf) {
        const int k0 = kt << 6;
        const uint32_t sb0 = sbase + buf * STAGE_B;
        // per tile: 128 rows x 8 chunks(16B) = 1024 chunks; 4 per thread
#pragma unroll
        for (int u = 0; u < 4; u++) {
            int f   = tid + u * 256;
            int row = f >> 3, c = f & 7;
            uint32_t soff = (uint32_t)(row * 144 + c * 16);
            cp16(sb0 + 0*TILE_B + soff, A + (size_t)(bm + row) * K + k0 + c * 8);
            cp16(sb0 + 1*TILE_B + soff, B + (size_t)(bn + row) * K + k0 + c * 8);
        }
    };

    const uint32_t aRowOff = (uint32_t)((wm*64 + (lane & 15)) * 144 + (lane >> 4) * 16);
    const uint32_t bRowOff = (uint32_t)((wn*32 + (lane & 15)) * 144 + (lane >> 4) * 16);

    load_stage(0, 0);
    asm volatile("cp.async.commit_group;");
    load_stage(1, 1);
    asm volatile("cp.async.commit_group;");

    for (int kt = 0; kt < nk; kt++) {
        if (kt < nk - 1) asm volatile("cp.async.wait_group 1;" ::: "memory");
        else             asm volatile("cp.async.wait_group 0;" ::: "memory");
        __syncthreads();

        const uint32_t sb0 = sbase + (uint32_t)(kt % NSTAGE) * STAGE_B;
#pragma unroll
        for (int ks = 0; ks < 4; ks++) {
            const uint32_t koff = ks * 32;
            uint32_t a[4][4], bb[2][4];
#pragma unroll
            for (int i = 0; i < 4; i++)
                ldmx4(a[i], sb0 + 0*TILE_B + aRowOff + (uint32_t)(i*16*144) + koff);
#pragma unroll
            for (int j = 0; j < 2; j++)
                ldmx4(bb[j], sb0 + 1*TILE_B + bRowOff + (uint32_t)(j*16*144) + koff);
#pragma unroll
            for (int i = 0; i < 4; i++)
#pragma unroll
                for (int nb = 0; nb < 4; nb++) {
                    int j = nb >> 1, sel = nb & 1;
                    mma16816(acc[i][nb], a[i], bb[j][sel], bb[j][sel + 2]);
                }
        }

        if (kt + 2 < nk) {
            load_stage(kt + 2, (kt + 2) % NSTAGE);
            asm volatile("cp.async.commit_group;");
        }
    }

    // --- epilogue ---
    const int mrow = bm + wm*64 + (lane >> 2);
    const int ncol = bnl + wn*32 + (lane & 3) * 2;
#pragma unroll
    for (int i = 0; i < 4; i++) {
#pragma unroll
        for (int jj = 0; jj < 4; jj++) {
            int r0 = mrow + i*16;
            int c  = ncol + jj*8;
            float2 bv = *(const float2*)(bias + c);
            float x0 = acc[i][jj][0] + bv.x;
            float x1 = acc[i][jj][1] + bv.y;
            float x2 = acc[i][jj][2] + bv.x;
            float x3 = acc[i][jj][3] + bv.y;
            if (MODE == 2) {
                x0 = fmaxf(x0, 0.f); x1 = fmaxf(x1, 0.f);
                x2 = fmaxf(x2, 0.f); x3 = fmaxf(x3, 0.f);
                *(__half2*)(Chx + (size_t)r0 * ldc + c)     = __floats2half2_rn(x0, x1);
                *(__half2*)(Chx + (size_t)(r0+8) * ldc + c) = __floats2half2_rn(x2, x3);
            } else if (MODE == 3) {
                *(__half2*)(Chx + (size_t)r0 * ldc + c)     = __floats2half2_rn(x0, x1);
                *(__half2*)(Chx + (size_t)(r0+8) * ldc + c) = __floats2half2_rn(x2, x3);
            } else {
                float2 rv0 = *(const float2*)(res + (size_t)r0 * ldc + c);
                float2 rv1 = *(const float2*)(res + (size_t)(r0+8) * ldc + c);
                x0 += rv0.x; x1 += rv0.y; x2 += rv1.x; x3 += rv1.y;
                *(float2*)(C0 + (size_t)r0 * ldc + c)     = make_float2(x0, x1);
                *(float2*)(C0 + (size_t)(r0+8) * ldc + c) = make_float2(x2, x3);
            }
        }
    }
}

// ---------------------------------------------------------------------------
// HMMA flash attention (fp16 in, fp32 accum, causal) -> fp16 z
// CTA: 128 q-rows x one (b,h); 8 warps, 16 q-rows/warp; KV tiles of 64,
// cp.async double buffer. (round-13 proven shape — untouched)
// ---------------------------------------------------------------------------
__global__ void __launch_bounds__(256) attn_hmma(
    const __half* __restrict__ Q, const __half* __restrict__ K,
    const __half* __restrict__ V, __half* __restrict__ Z)
{
    __shared__ __align__(16) __half sQ[128*72];
    __shared__ __align__(16) __half sK[2][64*72];
    __shared__ __align__(16) __half sV[2][64*72];
    const int tid = threadIdx.x, lane = tid & 31, wid = tid >> 5;
    const int qb = (SEQ/128 - 1) - blockIdx.x;      // heavy blocks first
    const int bh = blockIdx.y, b = bh >> 4, h = bh & 15;
    const uint32_t uQ = smem_to_u32(sQ);
    const uint32_t uK = smem_to_u32(sK);
    const uint32_t uV = smem_to_u32(sV);
    const size_t qbase = ((size_t)(b*SEQ + qb*128)) * D_MODEL + h * D_HEAD;

    for (int f = tid; f < 1024; f += 256) {
        int row = f >> 3, c = f & 7;
        cp16(uQ + row*144 + c*16, Q + qbase + (size_t)row * D_MODEL + c*8);
    }
    auto load_kv = [&](int kt, int buf) {
        size_t base = ((size_t)(b*SEQ + kt*64)) * D_MODEL + h * D_HEAD;
        for (int f = tid; f < 512; f += 256) {
            int row = f >> 3, c = f & 7;
            cp16(uK + buf*(64*144) + row*144 + c*16, K + base + (size_t)row * D_MODEL + c*8);
            cp16(uV + buf*(64*144) + row*144 + c*16, V + base + (size_t)row * D_MODEL + c*8);
        }
    };
    load_kv(0, 0);
    asm volatile("cp.async.commit_group;");

    float oacc[8][4];
#pragma unroll
    for (int i = 0; i < 8; i++)
#pragma unroll
        for (int c = 0; c < 4; c++) oacc[i][c] = 0.f;
    float m0 = -INFINITY, m1 = -INFINITY, l0 = 0.f, l1 = 0.f;
    uint32_t a[4][4];

    const int ntiles = 2*qb + 2;
    const int qwarp0 = qb*128 + wid*16;
    for (int kt = 0; kt < ntiles; kt++) {
        if (kt + 1 < ntiles) {
            load_kv(kt + 1, (kt + 1) & 1);
            asm volatile("cp.async.commit_group;");
            asm volatile("cp.async.wait_group 1;");
        } else {
            asm volatile("cp.async.wait_group 0;");
        }
        __syncthreads();

        if (kt == 0) {
#pragma unroll
            for (int kk = 0; kk < 4; kk++)
                ldmx4(a[kk], uQ + (uint32_t)((wid*16 + (lane & 15))*144 + kk*32 + (lane >> 4)*16));
        }

        const uint32_t kb0 = uK + (uint32_t)((kt & 1) * (64*144));
        float sc[8][4];
#pragma unroll
        for (int i = 0; i < 8; i++)
#pragma unroll
            for (int c = 0; c < 4; c++) sc[i][c] = 0.f;
#pragma unroll
        for (int kk = 0; kk < 4; kk++) {
            uint32_t kb[4][4];
#pragma unroll
            for (int j = 0; j < 4; j++)
                ldmx4(kb[j], kb0 + (uint32_t)((j*16 + (lane & 15))*144 + kk*32 + (lane >> 4)*16));
#pragma unroll
            for (int j = 0; j < 4; j++) {
                mma16816(sc[2*j],   a[kk], kb[j][0], kb[j][2]);
                mma16816(sc[2*j+1], a[kk], kb[j][1], kb[j][3]);
            }
        }

        const float scale = 0.125f;
        const bool diag = (kt*64 + 63) > qwarp0;
        const int qg0 = qwarp0 + (lane >> 2);
        float mx0 = m0, mx1 = m1;
#pragma unroll
        for (int nb = 0; nb < 8; nb++) {
#pragma unroll
            for (int c = 0; c < 4; c++) {
                float s = sc[nb][c] * scale;
                if (diag) {
                    int jg = kt*64 + nb*8 + (lane & 3)*2 + (c & 1);
                    int qg = qg0 + ((c >> 1) << 3);
                    if (jg > qg) s = -INFINITY;
                }
                sc[nb][c] = s;
            }
            mx0 = fmaxf(mx0, fmaxf(sc[nb][0], sc[nb][1]));
            mx1 = fmaxf(mx1, fmaxf(sc[nb][2], sc[nb][3]));
        }
        mx0 = fmaxf(mx0, __shfl_xor_sync(0xFFFFFFFFu, mx0, 1));
        mx0 = fmaxf(mx0, __shfl_xor_sync(0xFFFFFFFFu, mx0, 2));
        mx1 = fmaxf(mx1, __shfl_xor_sync(0xFFFFFFFFu, mx1, 1));
        mx1 = fmaxf(mx1, __shfl_xor_sync(0xFFFFFFFFu, mx1, 2));
        float fac0 = __expf(m0 - mx0), fac1 = __expf(m1 - mx1);
        m0 = mx0; m1 = mx1;
        float ls0 = 0.f, ls1 = 0.f;
#pragma unroll
        for (int nb = 0; nb < 8; nb++) {
            sc[nb][0] = __expf(sc[nb][0] - mx0);
            sc[nb][1] = __expf(sc[nb][1] - mx0);
            sc[nb][2] = __expf(sc[nb][2] - mx1);
            sc[nb][3] = __expf(sc[nb][3] - mx1);
            ls0 += sc[nb][0] + sc[nb][1];
            ls1 += sc[nb][2] + sc[nb][3];
        }
        l0 = l0 * fac0 + ls0;
        l1 = l1 * fac1 + ls1;
#pragma unroll
        for (int nb = 0; nb < 8; nb++) {
            oacc[nb][0] *= fac0; oacc[nb][1] *= fac0;
            oacc[nb][2] *= fac1; oacc[nb][3] *= fac1;
        }

        const uint32_t vb0 = uV + (uint32_t)((kt & 1) * (64*144));
#pragma unroll
        for (int kk = 0; kk < 4; kk++) {
            uint32_t pa[4];
            pa[0] = packh2(sc[2*kk][0],   sc[2*kk][1]);
            pa[1] = packh2(sc[2*kk][2],   sc[2*kk][3]);
            pa[2] = packh2(sc[2*kk+1][0], sc[2*kk+1][1]);
            pa[3] = packh2(sc[2*kk+1][2], sc[2*kk+1][3]);
#pragma unroll
            for (int j = 0; j < 4; j++) {
                uint32_t vb[4];
                ldmx4t(vb, vb0 + (uint32_t)((kk*16 + (lane & 15))*144 + j*32 + (lane >> 4)*16));
                mma16816(oacc[2*j],   pa, vb[0], vb[1]);
                mma16816(oacc[2*j+1], pa, vb[2], vb[3]);
            }
        }
        __syncthreads();
    }

    l0 += __shfl_xor_sync(0xFFFFFFFFu, l0, 1);
    l0 += __shfl_xor_sync(0xFFFFFFFFu, l0, 2);
    l1 += __shfl_xor_sync(0xFFFFFFFFu, l1, 1);
    l1 += __shfl_xor_sync(0xFFFFFFFFu, l1, 2);
    float i0 = 1.f / l0, i1 = 1.f / l1;
    size_t tok0 = (size_t)(b*SEQ + qb*128 + wid*16 + (lane >> 2));
    size_t zb0 = tok0 * D_MODEL + h * D_HEAD + (lane & 3)*2;
    size_t zb1 = zb0 + (size_t)8 * D_MODEL;
#pragma unroll
    for (int nb = 0; nb < 8; nb++) {
        *(__half2*)(Z + zb0 + nb*8) = __floats2half2_rn(oacc[nb][0]*i0, oacc[nb][1]*i0);
        *(__half2*)(Z + zb1 + nb*8) = __floats2half2_rn(oacc[nb][2]*i1, oacc[nb][3]*i1);
    }
}

// ---------------------------------------------------------------------------
// launch
// ---------------------------------------------------------------------------
extern "C" void kernel_launch(void* const* d_in, const int* in_sizes, int n_in,
                              void* d_out, int out_size) {
    const float* resid_pre = (const float*)d_in[0];
    const float* ln1_w = (const float*)d_in[1];
    const float* ln1_b = (const float*)d_in[2];
    const float* W_Q   = (const float*)d_in[3];
    const float* b_Q   = (const float*)d_in[4];
    const float* W_K   = (const float*)d_in[5];
    const float* b_K   = (const float*)d_in[6];
    const float* W_V   = (const float*)d_in[7];
    const float* b_V   = (const float*)d_in[8];
    const float* W_O   = (const float*)d_in[9];
    const float* b_O   = (const float*)d_in[10];
    const float* ln2_w = (const float*)d_in[11];
    const float* ln2_b = (const float*)d_in[12];
    const float* W_in  = (const float*)d_in[13];
    const float* b_in  = (const float*)d_in[14];
    const float* W_out = (const float*)d_in[15];
    const float* b_out = (const float*)d_in[16];
    float* out = (float*)d_out;

    __half *p_ln1, *p_q, *p_k, *p_v, *p_z, *p_ln2, *p_mlp, *p_wqkv, *p_wo, *p_win, *p_wout;
    float *p_rmid;

    cudaGetSymbolAddress((void**)&p_ln1,  g_ln1);
    cudaGetSymbolAddress((void**)&p_q,    g_q);
    cudaGetSymbolAddress((void**)&p_k,    g_k);
    cudaGetSymbolAddress((void**)&p_v,    g_v);
    cudaGetSymbolAddress((void**)&p_z,    g_z);
    cudaGetSymbolAddress((void**)&p_rmid, g_rmid);
    cudaGetSymbolAddress((void**)&p_ln2,  g_ln2);
    cudaGetSymbolAddress((void**)&p_mlp,  g_mlp);
    cudaGetSymbolAddress((void**)&p_wqkv, g_wqkv);
    cudaGetSymbolAddress((void**)&p_wo,   g_wo);
    cudaGetSymbolAddress((void**)&p_win,  g_win);
    cudaGetSymbolAddress((void**)&p_wout, g_wout);

    cudaFuncSetAttribute(gemm_h<1,false>, cudaFuncAttributeMaxDynamicSharedMemorySize, GEMM_SMEM);
    cudaFuncSetAttribute(gemm_h<2,false>, cudaFuncAttributeMaxDynamicSharedMemorySize, GEMM_SMEM);
    cudaFuncSetAttribute(gemm_h<3,true >, cudaFuncAttributeMaxDynamicSharedMemorySize, GEMM_SMEM);

    // 1) ALL weight transposes in one launch
    transpose_all<<<3072, 256>>>(W_Q, W_K, W_V, W_O, W_in, W_out,
                                 p_wqkv, p_wo, p_win, p_wout);

    // 2) LN1 -> fp16
    ln_h_kernel<<<NTOK, 256>>>(resid_pre, ln1_w, ln1_b, p_ln1);

    // 3) fused QKV projection -> fp16 q,k,v (segment-select)
    dim3 gQKV(3*D_MODEL/128, NTOK/128);
    gemm_h<3,true><<<gQKV, 256, GEMM_SMEM>>>(p_ln1, p_wqkv, b_Q, b_K, b_V, nullptr,
                                             nullptr, p_q, p_k, p_v, NTOK, 3*D_MODEL, D_MODEL);

    // 4) HMMA flash attention (128 q-rows/CTA) -> fp16 z
    attn_hmma<<<dim3(SEQ/128, BATCH*N_HEADS), 256>>>(p_q, p_k, p_v, p_z);

    // 5) O projection + residual -> rmid (fp32)
    dim3 gProj(D_MODEL/128, NTOK/128);
    gemm_h<1,false><<<gProj, 256, GEMM_SMEM>>>(p_z, p_wo, b_O, nullptr, nullptr, resid_pre,
                                               p_rmid, nullptr, nullptr, nullptr, NTOK, D_MODEL, D_MODEL);

    // 6) LN2 -> fp16
    ln_h_kernel<<<NTOK, 256>>>(p_rmid, ln2_w, ln2_b, p_ln2);

    // 7) MLP in + ReLU -> fp16
    dim3 gMlp1(D_MLP/128, NTOK/128);
    gemm_h<2,false><<<gMlp1, 256, GEMM_SMEM>>>(p_ln2, p_win, b_in, nullptr, nullptr, nullptr,
                                               nullptr, p_mlp, nullptr, nullptr, NTOK, D_MLP, D_MODEL);

    // 8) MLP out + residual -> output (fp32)
    gemm_h<1,false><<<gProj, 256, GEMM_SMEM>>>(p_mlp, p_wout, b_out, nullptr, nullptr, p_rmid,
                                               out, nullptr, nullptr, nullptr, NTOK, D_MODEL, D_MLP);
}

// round 16
// speedup vs baseline: 1.5389x; 1.0017x over previous
#include <cuda_runtime.h>
#include <cuda_fp16.h>
#include <math.h>
#include <stdint.h>

#define D_MODEL 1024
#define N_HEADS 16
#define D_HEAD  64
#define D_MLP   4096
#define BATCH   2
#define SEQ     2048
#define NTOK    (BATCH*SEQ)   // 4096
#define LN_EPS  1e-5f

// ---------------------------------------------------------------------------
// scratch (static device globals; no allocation)
// ---------------------------------------------------------------------------
__device__ __half g_ln1[NTOK*D_MODEL];
__device__ __half g_q  [NTOK*D_MODEL];
__device__ __half g_k  [NTOK*D_MODEL];
__device__ __half g_v  [NTOK*D_MODEL];
__device__ __half g_z  [NTOK*D_MODEL];
__device__ float  g_rmid[NTOK*D_MODEL];
__device__ __half g_ln2[NTOK*D_MODEL];
__device__ __half g_mlp[(size_t)NTOK*D_MLP];
// transposed fp16 weights ([N,K] row-major, k-contiguous)
__device__ __half g_wqkv[3*D_MODEL*D_MODEL];     // rows 0..1023 Q, 1024..2047 K, 2048..3071 V
__device__ __half g_wo  [D_MODEL*D_MODEL];
__device__ __half g_win [(size_t)D_MLP*D_MODEL];
__device__ __half g_wout[(size_t)D_MODEL*D_MLP];

// ---------------------------------------------------------------------------
// helpers
// ---------------------------------------------------------------------------
__device__ __forceinline__ uint32_t smem_to_u32(const void* p) {
    uint32_t a;
    asm("{ .reg .u64 t; cvta.to.shared.u64 t, %1; cvt.u32.u64 %0, t; }" : "=r"(a) : "l"(p));
    return a;
}
__device__ __forceinline__ void cp16(uint32_t s, const void* g) {
    asm volatile("cp.async.cg.shared.global [%0], [%1], 16;" :: "r"(s), "l"(g));
}
__device__ __forceinline__ void ldmx4(uint32_t* r, uint32_t addr) {
    asm volatile("ldmatrix.sync.aligned.m8n8.x4.shared.b16 {%0,%1,%2,%3}, [%4];"
        : "=r"(r[0]), "=r"(r[1]), "=r"(r[2]), "=r"(r[3]) : "r"(addr));
}
__device__ __forceinline__ void ldmx4t(uint32_t* r, uint32_t addr) {
    asm volatile("ldmatrix.sync.aligned.m8n8.x4.trans.shared.b16 {%0,%1,%2,%3}, [%4];"
        : "=r"(r[0]), "=r"(r[1]), "=r"(r[2]), "=r"(r[3]) : "r"(addr));
}
__device__ __forceinline__ void mma16816(float* d, const uint32_t* a, uint32_t b0, uint32_t b1) {
    asm volatile("mma.sync.aligned.m16n8k16.row.col.f32.f16.f16.f32 "
        "{%0,%1,%2,%3}, {%4,%5,%6,%7}, {%8,%9}, {%0,%1,%2,%3};"
        : "+f"(d[0]), "+f"(d[1]), "+f"(d[2]), "+f"(d[3])
        : "r"(a[0]), "r"(a[1]), "r"(a[2]), "r"(a[3]), "r"(b0), "r"(b1));
}
__device__ __forceinline__ uint32_t packh2(float x, float y) {
    __half2 h = __floats2half2_rn(x, y);
    return *(uint32_t*)&h;
}

// ---------------------------------------------------------------------------
// merged weight transpose: ALL weights in one launch (3072 blocks).
// ---------------------------------------------------------------------------
__global__ void transpose_all(const float* __restrict__ WQ, const float* __restrict__ WK,
                              const float* __restrict__ WV, const float* __restrict__ WO,
                              const float* __restrict__ Win, const float* __restrict__ Wout,
                              __half* __restrict__ wqkv, __half* __restrict__ wo,
                              __half* __restrict__ win, __half* __restrict__ wout) {
    __shared__ float t[64][65];
    const int bid = blockIdx.x;
    const float* src; __half* dst;
    int K, N, n0, k0;
    if (bid < 768) {
        int z = bid >> 4, kt = bid & 15;
        int seg = z >> 4, head = z & 15;
        src = (seg == 0 ? WQ : seg == 1 ? WK : WV) + (size_t)head * 1024 * 64;
        dst = wqkv + (size_t)seg * 1024 * 1024 + (size_t)head * 64 * 1024;
        K = 1024; N = 64; n0 = 0; k0 = kt * 64;
    } else if (bid < 1024) {
        int tt = bid - 768; n0 = (tt & 15) * 64; k0 = (tt >> 4) * 64;
        src = WO; dst = wo; K = 1024; N = 1024;
    } else if (bid < 2048) {
        int tt = bid - 1024; n0 = (tt & 63) * 64; k0 = (tt >> 6) * 64;
        src = Win; dst = win; K = 1024; N = 4096;
    } else {
        int tt = bid - 2048; n0 = (tt & 15) * 64; k0 = (tt >> 4) * 64;
        src = Wout; dst = wout; K = 4096; N = 1024;
    }
    const int tid = threadIdx.x;
    {
        int c4 = tid & 15, r = tid >> 4;
#pragma unroll
        for (int i = 0; i < 4; i++) {
            float4 v = *(const float4*)(src + (size_t)(k0 + r + i*16) * N + n0 + c4*4);
            t[r + i*16][c4*4+0] = v.x;
            t[r + i*16][c4*4+1] = v.y;
            t[r + i*16][c4*4+2] = v.z;
            t[r + i*16][c4*4+3] = v.w;
        }
    }
    __syncthreads();
    {
        int kg = (tid & 7) * 8;
#pragma unroll
        for (int p = 0; p < 2; p++) {
            int n = (tid >> 3) + p*32;
            __half h[8];
#pragma unroll
            for (int q = 0; q < 8; q++) h[q] = __float2half_rn(t[kg + q][n]);
            *(uint4*)(dst + (size_t)(n0 + n) * K + k0 + kg) = *(uint4*)h;
        }
    }
}

// ---------------------------------------------------------------------------
// LayerNorm -> fp16
// ---------------------------------------------------------------------------
__global__ void ln_h_kernel(const float* __restrict__ x, const float* __restrict__ w,
                            const float* __restrict__ b, __half* __restrict__ o) {
    int row = blockIdx.x;
    const float* xr = x + (size_t)row * D_MODEL;
    float vals[4];
    float s = 0.f, s2 = 0.f;
#pragma unroll
    for (int i = 0; i < 4; i++) {
        float v = xr[threadIdx.x + i*256];
        vals[i] = v; s += v; s2 += v*v;
    }
#pragma unroll
    for (int off = 16; off > 0; off >>= 1) {
        s  += __shfl_xor_sync(0xFFFFFFFFu, s,  off);
        s2 += __shfl_xor_sync(0xFFFFFFFFu, s2, off);
    }
    __shared__ float sh[2][8];
    int wid = threadIdx.x >> 5, lid = threadIdx.x & 31;
    if (lid == 0) { sh[0][wid] = s; sh[1][wid] = s2; }
    __syncthreads();
    s = 0.f; s2 = 0.f;
#pragma unroll
    for (int i = 0; i < 8; i++) { s += sh[0][i]; s2 += sh[1][i]; }
    float mean = s * (1.f/(float)D_MODEL);
    float var  = s2 * (1.f/(float)D_MODEL) - mean*mean;
    float rstd = rsqrtf(var + LN_EPS);
#pragma unroll
    for (int i = 0; i < 4; i++) {
        int c = threadIdx.x + i*256;
        float v = (vals[i] - mean) * rstd * w[c] + b[c];
        o[(size_t)row * D_MODEL + c] = __float2half_rn(v);
    }
}

// ---------------------------------------------------------------------------
// fp16 HMMA GEMM (round-14 proven shape): C[M,N] = A[M,K] @ B^T  (B [N,K] fp16)
// CTA tile 128x128, BK=64, 256 threads (8 warps 2x4, 64x32/warp),
// 3-stage cp.async pipeline, ONE sync per k-iter, 2 CTAs/SM. 144B rows.
// ---------------------------------------------------------------------------
#define TILE_B    18432              // 128 rows * 144 bytes
#define STAGE_B   (2*TILE_B)         // A + B tiles
#define NSTAGE    3
#define GEMM_SMEM (NSTAGE*STAGE_B)   // 110592

template<int MODE, bool SEG>
__global__ void __launch_bounds__(256, 2) gemm_h(
    const __half* __restrict__ A, const __half* __restrict__ B,
    const float* __restrict__ b0, const float* __restrict__ b1, const float* __restrict__ b2,
    const float* __restrict__ res,
    float* __restrict__ C0,
    __half* __restrict__ Ch0, __half* __restrict__ Ch1, __half* __restrict__ Ch2,
    int M, int N, int K)
{
    extern __shared__ __align__(128) char smem[];
    const uint32_t sbase = smem_to_u32(smem);
    const int tid  = threadIdx.x;
    const int lane = tid & 31;
    const int wid  = tid >> 5;
    const int wm   = wid >> 2;
    const int wn   = wid & 3;
    const int bm   = blockIdx.y * 128;
    const int bn   = blockIdx.x * 128;

    const float* bias = b0;
    __half* Chx = Ch0;
    int bnl = bn, ldc = N;
    if (SEG) {
        int sg = bn >> 10;
        bias = (sg == 0) ? b0 : (sg == 1) ? b1 : b2;
        Chx  = (sg == 0) ? Ch0 : (sg == 1) ? Ch1 : Ch2;
        bnl  = bn & 1023;
        ldc  = 1024;
    }

    float acc[4][4][4];
#pragma unroll
    for (int i = 0; i < 4; i++)
#pragma unroll
        for (int j = 0; j < 4; j++)
#pragma unroll
            for (int q = 0; q < 4; q++) acc[i][j][q] = 0.f;

    const int nk = K >> 6;   // BK = 64

    auto load_stage = [&](int kt, int buf) {
        const int k0 = kt << 6;
        const uint32_t sb0 = sbase + buf * STAGE_B;
#pragma unroll
        for (int u = 0; u < 4; u++) {
            int f   = tid + u * 256;
            int row = f >> 3, c = f & 7;
            uint32_t soff = (uint32_t)(row * 144 + c * 16);
            cp16(sb0 + 0*TILE_B + soff, A + (size_t)(bm + row) * K + k0 + c * 8);
            cp16(sb0 + 1*TILE_B + soff, B + (size_t)(bn + row) * K + k0 + c * 8);
        }
    };

    const uint32_t aRowOff = (uint32_t)((wm*64 + (lane & 15)) * 144 + (lane >> 4) * 16);
    const uint32_t bRowOff = (uint32_t)((wn*32 + (lane & 15)) * 144 + (lane >> 4) * 16);

    load_stage(0, 0);
    asm volatile("cp.async.commit_group;");
    load_stage(1, 1);
    asm volatile("cp.async.commit_group;");

    for (int kt = 0; kt < nk; kt++) {
        if (kt < nk - 1) asm volatile("cp.async.wait_group 1;" ::: "memory");
        else             asm volatile("cp.async.wait_group 0;" ::: "memory");
        __syncthreads();

        const uint32_t sb0 = sbase + (uint32_t)(kt % NSTAGE) * STAGE_B;
#pragma unroll
        for (int ks = 0; ks < 4; ks++) {
            const uint32_t koff = ks * 32;
            uint32_t a[4][4], bb[2][4];
#pragma unroll
            for (int i = 0; i < 4; i++)
                ldmx4(a[i], sb0 + 0*TILE_B + aRowOff + (uint32_t)(i*16*144) + koff);
#pragma unroll
            for (int j = 0; j < 2; j++)
                ldmx4(bb[j], sb0 + 1*TILE_B + bRowOff + (uint32_t)(j*16*144) + koff);
#pragma unroll
            for (int i = 0; i < 4; i++)
#pragma unroll
                for (int nb = 0; nb < 4; nb++) {
                    int j = nb >> 1, sel = nb & 1;
                    mma16816(acc[i][nb], a[i], bb[j][sel], bb[j][sel + 2]);
                }
        }

        if (kt + 2 < nk) {
            load_stage(kt + 2, (kt + 2) % NSTAGE);
            asm volatile("cp.async.commit_group;");
        }
    }

    // --- epilogue ---
    const int mrow = bm + wm*64 + (lane >> 2);
    const int ncol = bnl + wn*32 + (lane & 3) * 2;
#pragma unroll
    for (int i = 0; i < 4; i++) {
#pragma unroll
        for (int jj = 0; jj < 4; jj++) {
            int r0 = mrow + i*16;
            int c  = ncol + jj*8;
            float2 bv = *(const float2*)(bias + c);
            float x0 = acc[i][jj][0] + bv.x;
            float x1 = acc[i][jj][1] + bv.y;
            float x2 = acc[i][jj][2] + bv.x;
            float x3 = acc[i][jj][3] + bv.y;
            if (MODE == 2) {
                x0 = fmaxf(x0, 0.f); x1 = fmaxf(x1, 0.f);
                x2 = fmaxf(x2, 0.f); x3 = fmaxf(x3, 0.f);
                *(__half2*)(Chx + (size_t)r0 * ldc + c)     = __floats2half2_rn(x0, x1);
                *(__half2*)(Chx + (size_t)(r0+8) * ldc + c) = __floats2half2_rn(x2, x3);
            } else if (MODE == 3) {
                *(__half2*)(Chx + (size_t)r0 * ldc + c)     = __floats2half2_rn(x0, x1);
                *(__half2*)(Chx + (size_t)(r0+8) * ldc + c) = __floats2half2_rn(x2, x3);
            } else {
                float2 rv0 = *(const float2*)(res + (size_t)r0 * ldc + c);
                float2 rv1 = *(const float2*)(res + (size_t)(r0+8) * ldc + c);
                x0 += rv0.x; x1 += rv0.y; x2 += rv1.x; x3 += rv1.y;
                *(float2*)(C0 + (size_t)r0 * ldc + c)     = make_float2(x0, x1);
                *(float2*)(C0 + (size_t)(r0+8) * ldc + c) = make_float2(x2, x3);
            }
        }
    }
}

// ---------------------------------------------------------------------------
// HMMA flash attention (fp16 in, fp32 accum, causal) -> fp16 z
// CTA: 128 q-rows x one (b,h); 8 warps, 16 q-rows/warp.
// KV tiles of 128 (two 64-row sub-tiles per sync window), double-buffered.
// Per-warp skip of fully-masked sub-tiles on the diagonal tile.
// Dynamic smem: Q 18KB + K 2x18KB + V 2x18KB = 90KB -> 2 CTAs/SM.
// ---------------------------------------------------------------------------
#define ATTN_QB    0
#define ATTN_KB    18432              // 128*144
#define ATTN_VB    (18432 + 2*18432)
#define ATTN_SMEM  (18432 + 4*18432)  // 92160

__global__ void __launch_bounds__(256) attn_hmma(
    const __half* __restrict__ Q, const __half* __restrict__ K,
    const __half* __restrict__ V, __half* __restrict__ Z)
{
    extern __shared__ __align__(16) char asmem[];
    const int tid = threadIdx.x, lane = tid & 31, wid = tid >> 5;
    const int qb = (SEQ/128 - 1) - blockIdx.x;      // heavy blocks first
    const int bh = blockIdx.y, b = bh >> 4, h = bh & 15;
    const uint32_t uQ = smem_to_u32(asmem) + ATTN_QB;
    const uint32_t uK = smem_to_u32(asmem) + ATTN_KB;
    const uint32_t uV = smem_to_u32(asmem) + ATTN_VB;
    const size_t qbase = ((size_t)(b*SEQ + qb*128)) * D_MODEL + h * D_HEAD;

    // Q: 128 rows x 8 chunks
    for (int f = tid; f < 1024; f += 256) {
        int row = f >> 3, c = f & 7;
        cp16(uQ + row*144 + c*16, Q + qbase + (size_t)row * D_MODEL + c*8);
    }
    // K/V: 128-row tiles
    auto load_kv = [&](int kt, int buf) {
        size_t base = ((size_t)(b*SEQ + kt*128)) * D_MODEL + h * D_HEAD;
        for (int f = tid; f < 1024; f += 256) {
            int row = f >> 3, c = f & 7;
            cp16(uK + buf*(128*144) + row*144 + c*16, K + base + (size_t)row * D_MODEL + c*8);
            cp16(uV + buf*(128*144) + row*144 + c*16, V + base + (size_t)row * D_MODEL + c*8);
        }
    };
    load_kv(0, 0);
    asm volatile("cp.async.commit_group;");

    float oacc[8][4];
#pragma unroll
    for (int i = 0; i < 8; i++)
#pragma unroll
        for (int c = 0; c < 4; c++) oacc[i][c] = 0.f;
    float m0 = -INFINITY, m1 = -INFINITY, l0 = 0.f, l1 = 0.f;
    uint32_t a[4][4];

    const int nt = qb + 1;                          // 128-row KV tiles
    const int qwarp0 = qb*128 + wid*16;             // warp's first global q row
    for (int kt = 0; kt < nt; kt++) {
        if (kt + 1 < nt) {
            load_kv(kt + 1, (kt + 1) & 1);
            asm volatile("cp.async.commit_group;");
            asm volatile("cp.async.wait_group 1;");
        } else {
            asm volatile("cp.async.wait_group 0;");
        }
        __syncthreads();

        if (kt == 0) {
#pragma unroll
            for (int kk = 0; kk < 4; kk++)
                ldmx4(a[kk], uQ + (uint32_t)((wid*16 + (lane & 15))*144 + kk*32 + (lane >> 4)*16));
        }

        const uint32_t kbb = uK + (uint32_t)((kt & 1) * (128*144));
        const uint32_t vbb = uV + (uint32_t)((kt & 1) * (128*144));

#pragma unroll
        for (int s = 0; s < 2; s++) {
            const int j0 = kt*128 + s*64;           // sub-tile's first kv row
            if (j0 > qwarp0 + 15) continue;         // fully masked for this warp
            const uint32_t kb0 = kbb + (uint32_t)(s * 64 * 144);
            const uint32_t vb0 = vbb + (uint32_t)(s * 64 * 144);

            // S = Q K^T
            float sc[8][4];
#pragma unroll
            for (int i = 0; i < 8; i++)
#pragma unroll
                for (int c = 0; c < 4; c++) sc[i][c] = 0.f;
#pragma unroll
            for (int kk = 0; kk < 4; kk++) {
                uint32_t kb[4][4];
#pragma unroll
                for (int j = 0; j < 4; j++)
                    ldmx4(kb[j], kb0 + (uint32_t)((j*16 + (lane & 15))*144 + kk*32 + (lane >> 4)*16));
#pragma unroll
                for (int j = 0; j < 4; j++) {
                    mma16816(sc[2*j],   a[kk], kb[j][0], kb[j][2]);
                    mma16816(sc[2*j+1], a[kk], kb[j][1], kb[j][3]);
                }
            }

            // softmax (online), global-index causal mask
            const float scale = 0.125f;             // 1/sqrt(64)
            const bool diag = (j0 + 63) > qwarp0;
            const int qg0 = qwarp0 + (lane >> 2);
            float mx0 = m0, mx1 = m1;
#pragma unroll
            for (int nb = 0; nb < 8; nb++) {
#pragma unroll
                for (int c = 0; c < 4; c++) {
                    float sv = sc[nb][c] * scale;
                    if (diag) {
                        int jg = j0 + nb*8 + (lane & 3)*2 + (c & 1);
                        int qg = qg0 + ((c >> 1) << 3);
                        if (jg > qg) sv = -INFINITY;
                    }
                    sc[nb][c] = sv;
                }
                mx0 = fmaxf(mx0, fmaxf(sc[nb][0], sc[nb][1]));
                mx1 = fmaxf(mx1, fmaxf(sc[nb][2], sc[nb][3]));
            }
            mx0 = fmaxf(mx0, __shfl_xor_sync(0xFFFFFFFFu, mx0, 1));
            mx0 = fmaxf(mx0, __shfl_xor_sync(0xFFFFFFFFu, mx0, 2));
            mx1 = fmaxf(mx1, __shfl_xor_sync(0xFFFFFFFFu, mx1, 1));
            mx1 = fmaxf(mx1, __shfl_xor_sync(0xFFFFFFFFu, mx1, 2));
            float fac0 = __expf(m0 - mx0), fac1 = __expf(m1 - mx1);
            m0 = mx0; m1 = mx1;
            float ls0 = 0.f, ls1 = 0.f;
#pragma unroll
            for (int nb = 0; nb < 8; nb++) {
                sc[nb][0] = __expf(sc[nb][0] - mx0);
                sc[nb][1] = __expf(sc[nb][1] - mx0);
                sc[nb][2] = __expf(sc[nb][2] - mx1);
                sc[nb][3] = __expf(sc[nb][3] - mx1);
                ls0 += sc[nb][0] + sc[nb][1];
                ls1 += sc[nb][2] + sc[nb][3];
            }
            l0 = l0 * fac0 + ls0;
            l1 = l1 * fac1 + ls1;
#pragma unroll
            for (int nb = 0; nb < 8; nb++) {
                oacc[nb][0] *= fac0; oacc[nb][1] *= fac0;
                oacc[nb][2] *= fac1; oacc[nb][3] *= fac1;
            }

            // O += P V
#pragma unroll
            for (int kk = 0; kk < 4; kk++) {
                uint32_t pa[4];
                pa[0] = packh2(sc[2*kk][0],   sc[2*kk][1]);
                pa[1] = packh2(sc[2*kk][2],   sc[2*kk][3]);
                pa[2] = packh2(sc[2*kk+1][0], sc[2*kk+1][1]);
                pa[3] = packh2(sc[2*kk+1][2], sc[2*kk+1][3]);
#pragma unroll
                for (int j = 0; j < 4; j++) {
                    uint32_t vb[4];
                    ldmx4t(vb, vb0 + (uint32_t)((kk*16 + (lane & 15))*144 + j*32 + (lane >> 4)*16));
                    mma16816(oacc[2*j],   pa, vb[0], vb[1]);
                    mma16816(oacc[2*j+1], pa, vb[2], vb[3]);
                }
            }
        }
        __syncthreads();
    }

    // normalize + store
    l0 += __shfl_xor_sync(0xFFFFFFFFu, l0, 1);
    l0 += __shfl_xor_sync(0xFFFFFFFFu, l0, 2);
    l1 += __shfl_xor_sync(0xFFFFFFFFu, l1, 1);
    l1 += __shfl_xor_sync(0xFFFFFFFFu, l1, 2);
    float i0 = 1.f / l0, i1 = 1.f / l1;
    size_t tok0 = (size_t)(b*SEQ + qb*128 + wid*16 + (lane >> 2));
    size_t zb0 = tok0 * D_MODEL + h * D_HEAD + (lane & 3)*2;
    size_t zb1 = zb0 + (size_t)8 * D_MODEL;
#pragma unroll
    for (int nb = 0; nb < 8; nb++) {
        *(__half2*)(Z + zb0 + nb*8) = __floats2half2_rn(oacc[nb][0]*i0, oacc[nb][1]*i0);
        *(__half2*)(Z + zb1 + nb*8) = __floats2half2_rn(oacc[nb][2]*i1, oacc[nb][3]*i1);
    }
}

// ---------------------------------------------------------------------------
// launch
// ---------------------------------------------------------------------------
extern "C" void kernel_launch(void* const* d_in, const int* in_sizes, int n_in,
                              void* d_out, int out_size) {
    const float* resid_pre = (const float*)d_in[0];
    const float* ln1_w = (const float*)d_in[1];
    const float* ln1_b = (const float*)d_in[2];
    const float* W_Q   = (const float*)d_in[3];
    const float* b_Q   = (const float*)d_in[4];
    const float* W_K   = (const float*)d_in[5];
    const float* b_K   = (const float*)d_in[6];
    const float* W_V   = (const float*)d_in[7];
    const float* b_V   = (const float*)d_in[8];
    const float* W_O   = (const float*)d_in[9];
    const float* b_O   = (const float*)d_in[10];
    const float* ln2_w = (const float*)d_in[11];
    const float* ln2_b = (const float*)d_in[12];
    const float* W_in  = (const float*)d_in[13];
    const float* b_in  = (const float*)d_in[14];
    const float* W_out = (const float*)d_in[15];
    const float* b_out = (const float*)d_in[16];
    float* out = (float*)d_out;

    __half *p_ln1, *p_q, *p_k, *p_v, *p_z, *p_ln2, *p_mlp, *p_wqkv, *p_wo, *p_win, *p_wout;
    float *p_rmid;

    cudaGetSymbolAddress((void**)&p_ln1,  g_ln1);
    cudaGetSymbolAddress((void**)&p_q,    g_q);
    cudaGetSymbolAddress((void**)&p_k,    g_k);
    cudaGetSymbolAddress((void**)&p_v,    g_v);
    cudaGetSymbolAddress((void**)&p_z,    g_z);
    cudaGetSymbolAddress((void**)&p_rmid, g_rmid);
    cudaGetSymbolAddress((void**)&p_ln2,  g_ln2);
    cudaGetSymbolAddress((void**)&p_mlp,  g_mlp);
    cudaGetSymbolAddress((void**)&p_wqkv, g_wqkv);
    cudaGetSymbolAddress((void**)&p_wo,   g_wo);
    cudaGetSymbolAddress((void**)&p_win,  g_win);
    cudaGetSymbolAddress((void**)&p_wout, g_wout);

    cudaFuncSetAttribute(gemm_h<1,false>, cudaFuncAttributeMaxDynamicSharedMemorySize, GEMM_SMEM);
    cudaFuncSetAttribute(gemm_h<2,false>, cudaFuncAttributeMaxDynamicSharedMemorySize, GEMM_SMEM);
    cudaFuncSetAttribute(gemm_h<3,true >, cudaFuncAttributeMaxDynamicSharedMemorySize, GEMM_SMEM);
    cudaFuncSetAttribute(attn_hmma, cudaFuncAttributeMaxDynamicSharedMemorySize, ATTN_SMEM);

    // 1) ALL weight transposes in one launch
    transpose_all<<<3072, 256>>>(W_Q, W_K, W_V, W_O, W_in, W_out,
                                 p_wqkv, p_wo, p_win, p_wout);

    // 2) LN1 -> fp16
    ln_h_kernel<<<NTOK, 256>>>(resid_pre, ln1_w, ln1_b, p_ln1);

    // 3) fused QKV projection -> fp16 q,k,v (segment-select)
    dim3 gQKV(3*D_MODEL/128, NTOK/128);
    gemm_h<3,true><<<gQKV, 256, GEMM_SMEM>>>(p_ln1, p_wqkv, b_Q, b_K, b_V, nullptr,
                                             nullptr, p_q, p_k, p_v, NTOK, 3*D_MODEL, D_MODEL);

    // 4) HMMA flash attention (128 q-rows/CTA, 128-row KV tiles) -> fp16 z
    attn_hmma<<<dim3(SEQ/128, BATCH*N_HEADS), 256, ATTN_SMEM>>>(p_q, p_k, p_v, p_z);

    // 5) O projection + residual -> rmid (fp32)
    dim3 gProj(D_MODEL/128, NTOK/128);
    gemm_h<1,false><<<gProj, 256, GEMM_SMEM>>>(p_z, p_wo, b_O, nullptr, nullptr, resid_pre,
                                               p_rmid, nullptr, nullptr, nullptr, NTOK, D_MODEL, D_MODEL);

    // 6) LN2 -> fp16
    ln_h_kernel<<<NTOK, 256>>>(p_rmid, ln2_w, ln2_b, p_ln2);

    // 7) MLP in + ReLU -> fp16
    dim3 gMlp1(D_MLP/128, NTOK/128);
    gemm_h<2,false><<<gMlp1, 256, GEMM_SMEM>>>(p_ln2, p_win, b_in, nullptr, nullptr, nullptr,
                                               nullptr, p_mlp, nullptr, nullptr, NTOK, D_MLP, D_MODEL);

    // 8) MLP out + residual -> output (fp32)
    gemm_h<1,false><<<gProj, 256, GEMM_SMEM>>>(p_mlp, p_wout, b_out, nullptr, nullptr, p_rmid,
                                               out, nullptr, nullptr, nullptr, NTOK, D_MODEL, D_MLP);
}